// round 2
// baseline (speedup 1.0000x reference)
#include <cuda_runtime.h>

// Problem constants
constexpr int DM = 1024;    // d_model
constexpr int NH = 16;      // heads
constexpr int DH = 64;      // head dim
constexpr int BB = 2;       // batch
constexpr int SS = 2048;    // seq len
constexpr int MT = BB * SS; // 4096 tokens

// Scratch (device globals -- no allocations allowed)
__device__ float g_q[MT * DM];
__device__ float g_k[MT * DM];
__device__ float g_v[MT * DM];
__device__ float g_attn[MT * DM];

// ---------------------------------------------------------------------------
// SGEMM NT:  Y[M,N] = X[M,K] @ W[N,K]^T (+ bias)
// BM=BN=128, BK=16, 256 threads, 8x8 micro-tile per thread.
// N == K == 1024 fixed for this problem.
// ---------------------------------------------------------------------------
__device__ __forceinline__ void sgemm_nt_body(
    const float* __restrict__ X, const float* __restrict__ W,
    const float* __restrict__ bias, float* __restrict__ Y)
{
    __shared__ float As[16][132];
    __shared__ float Bs[16][132];

    const int bm  = blockIdx.y * 128;
    const int bn  = blockIdx.x * 128;
    const int tid = threadIdx.x;
    const int tx  = tid & 15;   // 0..15
    const int ty  = tid >> 4;   // 0..15

    float acc[8][8];
#pragma unroll
    for (int i = 0; i < 8; i++)
#pragma unroll
        for (int j = 0; j < 8; j++) acc[i][j] = 0.f;

    for (int k0 = 0; k0 < 1024; k0 += 16) {
        // Load 128x16 tiles of X and W, transposed into smem [k][m]
#pragma unroll
        for (int i = 0; i < 2; i++) {
            int v  = tid + 256 * i;
            int m  = v >> 2;
            int k4 = v & 3;
            float4 a = *(const float4*)(X + (size_t)(bm + m) * 1024 + k0 + k4 * 4);
            As[k4 * 4 + 0][m] = a.x;
            As[k4 * 4 + 1][m] = a.y;
            As[k4 * 4 + 2][m] = a.z;
            As[k4 * 4 + 3][m] = a.w;
            float4 b = *(const float4*)(W + (size_t)(bn + m) * 1024 + k0 + k4 * 4);
            Bs[k4 * 4 + 0][m] = b.x;
            Bs[k4 * 4 + 1][m] = b.y;
            Bs[k4 * 4 + 2][m] = b.z;
            Bs[k4 * 4 + 3][m] = b.w;
        }
        __syncthreads();

#pragma unroll
        for (int kk = 0; kk < 16; kk++) {
            float4 a0 = *(const float4*)&As[kk][ty * 8];
            float4 a1 = *(const float4*)&As[kk][ty * 8 + 4];
            float4 b0 = *(const float4*)&Bs[kk][tx * 8];
            float4 b1 = *(const float4*)&Bs[kk][tx * 8 + 4];
            float av[8] = {a0.x, a0.y, a0.z, a0.w, a1.x, a1.y, a1.z, a1.w};
            float bv[8] = {b0.x, b0.y, b0.z, b0.w, b1.x, b1.y, b1.z, b1.w};
#pragma unroll
            for (int i = 0; i < 8; i++)
#pragma unroll
                for (int j = 0; j < 8; j++) acc[i][j] += av[i] * bv[j];
        }
        __syncthreads();
    }

    // Epilogue
    float bb2[8];
#pragma unroll
    for (int j = 0; j < 8; j++) bb2[j] = bias ? bias[bn + tx * 8 + j] : 0.f;

#pragma unroll
    for (int i = 0; i < 8; i++) {
        int rowm = bm + ty * 8 + i;
        float* yp = Y + (size_t)rowm * 1024 + bn + tx * 8;
        float4 c0 = make_float4(acc[i][0] + bb2[0], acc[i][1] + bb2[1],
                                acc[i][2] + bb2[2], acc[i][3] + bb2[3]);
        float4 c1 = make_float4(acc[i][4] + bb2[4], acc[i][5] + bb2[5],
                                acc[i][6] + bb2[6], acc[i][7] + bb2[7]);
        *(float4*)(yp)     = c0;
        *(float4*)(yp + 4) = c1;
    }
}

__global__ __launch_bounds__(256) void qkv_gemm(
    const float* __restrict__ X,
    const float* __restrict__ Wq,
    const float* __restrict__ Wk,
    const float* __restrict__ Wv)
{
    const float* W = (blockIdx.z == 0) ? Wq : (blockIdx.z == 1) ? Wk : Wv;
    float* Y = (blockIdx.z == 0) ? g_q : (blockIdx.z == 1) ? g_k : g_v;
    sgemm_nt_body(X, W, nullptr, Y);
}

__global__ __launch_bounds__(256) void o_gemm(
    const float* __restrict__ Wo,
    const float* __restrict__ bo,
    float* __restrict__ out)
{
    sgemm_nt_body(g_attn, Wo, bo, out);
}

// ---------------------------------------------------------------------------
// Causal flash attention, fp32.
// grid = (S/128, B*H), block = 128 threads. Each thread owns one q row:
// q (64 floats) and output acc (64 floats) live in registers; K/V tiles of
// 32 rows in smem (float4 broadcast reads); streaming softmax.
// ---------------------------------------------------------------------------
__global__ __launch_bounds__(128) void attn_kernel()
{
    const int qt  = blockIdx.x;            // 0..15
    const int bh  = blockIdx.y;            // 0..31
    const int b   = bh / NH;
    const int h   = bh % NH;
    const int tid = threadIdx.x;
    const int row = qt * 128 + tid;        // global query index (< S)

    __shared__ float4 Ks4[32 * 16];        // 32 kv rows x 64 dims
    __shared__ float4 Vs4[32 * 16];
    __shared__ float  Ss[128][33];         // per-thread scores, padded

    float4 q4[16], acc4[16];
    const float* qp = g_q + ((size_t)(b * SS + row)) * DM + h * DH;
#pragma unroll
    for (int i = 0; i < 16; i++) {
        q4[i]   = ((const float4*)qp)[i];
        acc4[i] = make_float4(0.f, 0.f, 0.f, 0.f);
    }

    float mrun = -1e30f, lrun = 0.f;
    const float scale = 0.125f;            // 1/sqrt(64)

    const int ntiles = qt * 4 + 4;         // kv tiles needed for this q block
    for (int t = 0; t < ntiles; t++) {
        const int j0 = t * 32;
        // cooperative K/V tile load
#pragma unroll
        for (int i = 0; i < 4; i++) {
            int idx = tid + 128 * i;
            int j   = idx >> 4;
            int d4  = idx & 15;
            size_t base = ((size_t)(b * SS + j0 + j)) * DM + h * DH;
            Ks4[idx] = ((const float4*)(g_k + base))[d4];
            Vs4[idx] = ((const float4*)(g_v + base))[d4];
        }
        __syncthreads();

        int nv = row - j0 + 1;
        nv = nv < 0 ? 0 : (nv > 32 ? 32 : nv);

        float tmax = -1e30f;
        for (int j = 0; j < nv; j++) {
            float s = 0.f;
#pragma unroll
            for (int d = 0; d < 16; d++) {
                float4 k4 = Ks4[j * 16 + d];
                s += q4[d].x * k4.x + q4[d].y * k4.y +
                     q4[d].z * k4.z + q4[d].w * k4.w;
            }
            s *= scale;
            Ss[tid][j] = s;
            tmax = fmaxf(tmax, s);
        }

        if (nv > 0) {
            float mnew = fmaxf(mrun, tmax);
            float corr = __expf(mrun - mnew);
            lrun *= corr;
#pragma unroll
            for (int d = 0; d < 16; d++) {
                acc4[d].x *= corr; acc4[d].y *= corr;
                acc4[d].z *= corr; acc4[d].w *= corr;
            }
            for (int j = 0; j < nv; j++) {
                float p = __expf(Ss[tid][j] - mnew);
                lrun += p;
#pragma unroll
                for (int d = 0; d < 16; d++) {
                    float4 v4 = Vs4[j * 16 + d];
                    acc4[d].x += p * v4.x;
                    acc4[d].y += p * v4.y;
                    acc4[d].z += p * v4.z;
                    acc4[d].w += p * v4.w;
                }
            }
            mrun = mnew;
        }
        __syncthreads();
    }

    const float inv = 1.f / lrun;
    float* op = g_attn + ((size_t)(b * SS + row)) * DM + h * DH;
#pragma unroll
    for (int d = 0; d < 16; d++) {
        float4 o = make_float4(acc4[d].x * inv, acc4[d].y * inv,
                               acc4[d].z * inv, acc4[d].w * inv);
        ((float4*)op)[d] = o;
    }
}

// ---------------------------------------------------------------------------
extern "C" void kernel_launch(void* const* d_in, const int* in_sizes, int n_in,
                              void* d_out, int out_size)
{
    const float* x  = (const float*)d_in[0];
    const float* Wq = (const float*)d_in[1];
    const float* Wk = (const float*)d_in[2];
    const float* Wv = (const float*)d_in[3];
    const float* Wo = (const float*)d_in[4];
    const float* bo = (const float*)d_in[5];
    float* out = (float*)d_out;

    dim3 gqkv(DM / 128, MT / 128, 3);   // 8 x 32 x 3
    qkv_gemm<<<gqkv, 256>>>(x, Wq, Wk, Wv);

    dim3 gattn(SS / 128, BB * NH);      // 16 x 32
    attn_kernel<<<gattn, 128>>>();

    dim3 go(DM / 128, MT / 128);        // 8 x 32
    o_gemm<<<go, 256>>>(Wo, bo, out);
}

// round 4
// speedup vs baseline: 1.3717x; 1.3717x over previous
#include <cuda_runtime.h>
#include <cuda_bf16.h>
#include <cstdint>

// Problem constants
constexpr int DM = 1024;    // d_model
constexpr int NH = 16;      // heads
constexpr int DH = 64;      // head dim
constexpr int BB = 2;       // batch
constexpr int SS = 2048;    // seq len
constexpr int MT = BB * SS; // 4096 tokens

// ---------------------------------------------------------------------------
// Scratch (device globals -- no allocations allowed)
// ---------------------------------------------------------------------------
__device__ float g_q[MT * DM];
__device__ float g_k[MT * DM];
__device__ float g_v[MT * DM];
__device__ float g_attn[MT * DM];

// bf16 hi/lo split planes
__device__ __nv_bfloat16 g_xhi[MT * DM];
__device__ __nv_bfloat16 g_xlo[MT * DM];
__device__ __nv_bfloat16 g_wqhi[DM * DM];
__device__ __nv_bfloat16 g_wqlo[DM * DM];
__device__ __nv_bfloat16 g_wkhi[DM * DM];
__device__ __nv_bfloat16 g_wklo[DM * DM];
__device__ __nv_bfloat16 g_wvhi[DM * DM];
__device__ __nv_bfloat16 g_wvlo[DM * DM];
__device__ __nv_bfloat16 g_wohi[DM * DM];
__device__ __nv_bfloat16 g_wolo[DM * DM];
__device__ __nv_bfloat16 g_ahi[MT * DM];
__device__ __nv_bfloat16 g_alo[MT * DM];

// ---------------------------------------------------------------------------
// PTX helpers (sm_80-baseline features only: cp.async, ldmatrix, mma.sync)
// ---------------------------------------------------------------------------
__device__ __forceinline__ uint32_t smem_to_u32(const void* p) {
    uint32_t a;
    asm("{ .reg .u64 t; cvta.to.shared.u64 t, %1; cvt.u32.u64 %0, t; }"
        : "=r"(a) : "l"(p));
    return a;
}

__device__ __forceinline__ void cp_async16(uint32_t dst, const void* src) {
    asm volatile("cp.async.cg.shared.global [%0], [%1], 16;"
                 :: "r"(dst), "l"(src) : "memory");
}
#define CP_COMMIT() asm volatile("cp.async.commit_group;" ::: "memory")
template <int N>
__device__ __forceinline__ void cp_wait() {
    asm volatile("cp.async.wait_group %0;" :: "n"(N) : "memory");
}

__device__ __forceinline__ void ldmx4(uint32_t (&r)[4], uint32_t addr) {
    asm volatile("ldmatrix.sync.aligned.m8n8.x4.shared.b16 {%0,%1,%2,%3}, [%4];"
                 : "=r"(r[0]), "=r"(r[1]), "=r"(r[2]), "=r"(r[3]) : "r"(addr));
}

__device__ __forceinline__ void mma16816(float (&c)[4], const uint32_t (&a)[4],
                                         uint32_t b0, uint32_t b1) {
    asm volatile(
        "mma.sync.aligned.m16n8k16.row.col.f32.bf16.bf16.f32 "
        "{%0,%1,%2,%3}, {%4,%5,%6,%7}, {%8,%9}, {%0,%1,%2,%3};"
        : "+f"(c[0]), "+f"(c[1]), "+f"(c[2]), "+f"(c[3])
        : "r"(a[0]), "r"(a[1]), "r"(a[2]), "r"(a[3]), "r"(b0), "r"(b1));
}

// Swizzled offset inside a 128-row x 32-bf16 (64B/row) tile.
// chunk = kg ^ ((row>>1)&3): conflict-free for cp.async writes and ldmatrix.
__device__ __forceinline__ uint32_t tile_off(int row, int kg) {
    return (uint32_t)(row * 64 + (((kg ^ ((row >> 1) & 3)) & 3) << 4));
}

// ---------------------------------------------------------------------------
// hi/lo bf16 split conversion
// ---------------------------------------------------------------------------
__global__ __launch_bounds__(256) void split_bf16(const float* __restrict__ src,
                                                  __nv_bfloat16* __restrict__ hi,
                                                  __nv_bfloat16* __restrict__ lo, int n) {
    int i = blockIdx.x * 256 + threadIdx.x;
    if (i < n) {
        float x = src[i];
        __nv_bfloat16 h = __float2bfloat16(x);
        hi[i] = h;
        lo[i] = __float2bfloat16(x - __bfloat162float(h));
    }
}

// ---------------------------------------------------------------------------
// bf16x3 tensor-core GEMM:  Y[M,N] = A[M,K] @ B[N,K]^T (+bias),  fp32 out.
// A ~ Ah+Al, B ~ Bh+Bl;  Y = Ah*Bh + Ah*Bl + Al*Bh  (fp32 accum).
// CTA: 128x128 tile, K chunked by 32, double-buffered cp.async.
// 512 threads = 16 warps in 4(m) x 4(n) grid; warp tile 32x32.
// SMEM per stage: Ah|Al|Bh|Bl, each 128x32 bf16 = 8KB -> 32KB; 2 stages.
// ---------------------------------------------------------------------------
constexpr int GEMM_SMEM = 2 * 32768;

__device__ __forceinline__ void stage_load(
    uint32_t sbase, int st,
    const __nv_bfloat16* __restrict__ Ah, const __nv_bfloat16* __restrict__ Al,
    const __nv_bfloat16* __restrict__ Bh, const __nv_bfloat16* __restrict__ Bl,
    int bm, int bn, int k0, int lrow, int lkg, uint32_t ldst)
{
    const uint32_t base = sbase + st * 32768 + ldst;
    const __nv_bfloat16* planes[4] = {Ah, Al, Bh, Bl};
#pragma unroll
    for (int pl = 0; pl < 4; pl++) {
        int rowbase = (pl < 2) ? bm : bn;
        const __nv_bfloat16* src =
            planes[pl] + (size_t)(rowbase + lrow) * 1024 + k0 + lkg * 8;
        cp_async16(base + pl * 8192, src);
    }
}

__device__ __forceinline__ void mma_gemm_body(
    const __nv_bfloat16* __restrict__ Ah, const __nv_bfloat16* __restrict__ Al,
    const __nv_bfloat16* __restrict__ Bh, const __nv_bfloat16* __restrict__ Bl,
    const float* __restrict__ bias, float* __restrict__ Y)
{
    extern __shared__ char smem[];
    const uint32_t sbase = smem_to_u32(smem);
    const int tid  = threadIdx.x;
    const int wid  = tid >> 5;
    const int lane = tid & 31;
    const int m_base = (wid & 3) * 32;
    const int n_base = (wid >> 2) * 32;
    const int bm = blockIdx.y * 128;
    const int bn = blockIdx.x * 128;

    // loader mapping: thread -> one 16B chunk per tile
    const int lrow = tid >> 2;
    const int lkg  = tid & 3;
    const uint32_t ldst = tile_off(lrow, lkg);

    float acc[2][4][4];
#pragma unroll
    for (int mt = 0; mt < 2; mt++)
#pragma unroll
        for (int nt = 0; nt < 4; nt++)
#pragma unroll
            for (int i = 0; i < 4; i++) acc[mt][nt][i] = 0.f;

    stage_load(sbase, 0, Ah, Al, Bh, Bl, bm, bn, 0, lrow, lkg, ldst);
    CP_COMMIT();

    for (int kc = 0; kc < 32; kc++) {
        if (kc < 31) {
            stage_load(sbase, (kc + 1) & 1, Ah, Al, Bh, Bl, bm, bn,
                       (kc + 1) * 32, lrow, lkg, ldst);
            CP_COMMIT();
            cp_wait<1>();
        } else {
            cp_wait<0>();
        }
        __syncthreads();

        const uint32_t st = sbase + (kc & 1) * 32768;
#pragma unroll
        for (int s = 0; s < 2; s++) {
            uint32_t ah[2][4], al[2][4], bh[2][4], bl[2][4];
            // A fragments (two m16 tiles, hi & lo planes)
            {
                int r   = lane & 7;
                int sel = lane >> 3;
                int kg  = 2 * s + (sel >> 1);
#pragma unroll
                for (int mt = 0; mt < 2; mt++) {
                    int row = m_base + mt * 16 + r + ((sel & 1) << 3);
                    uint32_t off = tile_off(row, kg);
                    ldmx4(ah[mt], st + off);
                    ldmx4(al[mt], st + 8192 + off);
                }
            }
            // B fragments (two n16 groups, hi & lo planes)
            {
                int r  = lane & 7;
                int kg = 2 * s + ((lane >> 3) & 1);
#pragma unroll
                for (int ng = 0; ng < 2; ng++) {
                    int row = n_base + ng * 16 + r + ((lane >> 4) << 3);
                    uint32_t off = tile_off(row, kg);
                    ldmx4(bh[ng], st + 16384 + off);
                    ldmx4(bl[ng], st + 24576 + off);
                }
            }
#pragma unroll
            for (int mt = 0; mt < 2; mt++)
#pragma unroll
                for (int nt = 0; nt < 4; nt++) {
                    int g = nt >> 1, o = (nt & 1) * 2;
                    mma16816(acc[mt][nt], ah[mt], bh[g][o], bh[g][o + 1]);
                    mma16816(acc[mt][nt], ah[mt], bl[g][o], bl[g][o + 1]);
                    mma16816(acc[mt][nt], al[mt], bh[g][o], bh[g][o + 1]);
                }
        }
        __syncthreads();
    }

    // Epilogue: fragment -> gmem fp32 (+bias)
    const int gid = lane >> 2;   // 0..7
    const int tig = lane & 3;    // 0..3
#pragma unroll
    for (int mt = 0; mt < 2; mt++) {
#pragma unroll
        for (int nt = 0; nt < 4; nt++) {
            int row0 = bm + m_base + mt * 16 + gid;
            int col0 = bn + n_base + nt * 8 + tig * 2;
            float b0 = bias ? bias[col0]     : 0.f;
            float b1 = bias ? bias[col0 + 1] : 0.f;
            float2 v0 = make_float2(acc[mt][nt][0] + b0, acc[mt][nt][1] + b1);
            float2 v1 = make_float2(acc[mt][nt][2] + b0, acc[mt][nt][3] + b1);
            *(float2*)(Y + (size_t)row0 * 1024 + col0)       = v0;
            *(float2*)(Y + (size_t)(row0 + 8) * 1024 + col0) = v1;
        }
    }
}

__global__ __launch_bounds__(512) void qkv_mma() {
    const __nv_bfloat16 *Bh, *Bl;
    float* Y;
    if (blockIdx.z == 0)      { Bh = g_wqhi; Bl = g_wqlo; Y = g_q; }
    else if (blockIdx.z == 1) { Bh = g_wkhi; Bl = g_wklo; Y = g_k; }
    else                      { Bh = g_wvhi; Bl = g_wvlo; Y = g_v; }
    mma_gemm_body(g_xhi, g_xlo, Bh, Bl, nullptr, Y);
}

__global__ __launch_bounds__(512) void o_mma(const float* __restrict__ bo,
                                             float* __restrict__ out) {
    mma_gemm_body(g_ahi, g_alo, g_wohi, g_wolo, bo, out);
}

// ---------------------------------------------------------------------------
// Causal flash attention, fp32 (unchanged; tensorize next round).
// ---------------------------------------------------------------------------
__global__ __launch_bounds__(128) void attn_kernel()
{
    const int qt  = blockIdx.x;
    const int bh  = blockIdx.y;
    const int b   = bh / NH;
    const int h   = bh % NH;
    const int tid = threadIdx.x;
    const int row = qt * 128 + tid;

    __shared__ float4 Ks4[32 * 16];
    __shared__ float4 Vs4[32 * 16];
    __shared__ float  Ss[128][33];

    float4 q4[16], acc4[16];
    const float* qp = g_q + ((size_t)(b * SS + row)) * DM + h * DH;
#pragma unroll
    for (int i = 0; i < 16; i++) {
        q4[i]   = ((const float4*)qp)[i];
        acc4[i] = make_float4(0.f, 0.f, 0.f, 0.f);
    }

    float mrun = -1e30f, lrun = 0.f;
    const float scale = 0.125f;

    const int ntiles = qt * 4 + 4;
    for (int t = 0; t < ntiles; t++) {
        const int j0 = t * 32;
#pragma unroll
        for (int i = 0; i < 4; i++) {
            int idx = tid + 128 * i;
            int j   = idx >> 4;
            int d4  = idx & 15;
            size_t base = ((size_t)(b * SS + j0 + j)) * DM + h * DH;
            Ks4[idx] = ((const float4*)(g_k + base))[d4];
            Vs4[idx] = ((const float4*)(g_v + base))[d4];
        }
        __syncthreads();

        int nv = row - j0 + 1;
        nv = nv < 0 ? 0 : (nv > 32 ? 32 : nv);

        float tmax = -1e30f;
        for (int j = 0; j < nv; j++) {
            float s = 0.f;
#pragma unroll
            for (int d = 0; d < 16; d++) {
                float4 k4 = Ks4[j * 16 + d];
                s += q4[d].x * k4.x + q4[d].y * k4.y +
                     q4[d].z * k4.z + q4[d].w * k4.w;
            }
            s *= scale;
            Ss[tid][j] = s;
            tmax = fmaxf(tmax, s);
        }

        if (nv > 0) {
            float mnew = fmaxf(mrun, tmax);
            float corr = __expf(mrun - mnew);
            lrun *= corr;
#pragma unroll
            for (int d = 0; d < 16; d++) {
                acc4[d].x *= corr; acc4[d].y *= corr;
                acc4[d].z *= corr; acc4[d].w *= corr;
            }
            for (int j = 0; j < nv; j++) {
                float p = __expf(Ss[tid][j] - mnew);
                lrun += p;
#pragma unroll
                for (int d = 0; d < 16; d++) {
                    float4 v4 = Vs4[j * 16 + d];
                    acc4[d].x += p * v4.x;
                    acc4[d].y += p * v4.y;
                    acc4[d].z += p * v4.z;
                    acc4[d].w += p * v4.w;
                }
            }
            mrun = mnew;
        }
        __syncthreads();
    }

    const float inv = 1.f / lrun;
    float* op = g_attn + ((size_t)(b * SS + row)) * DM + h * DH;
#pragma unroll
    for (int d = 0; d < 16; d++) {
        float4 o = make_float4(acc4[d].x * inv, acc4[d].y * inv,
                               acc4[d].z * inv, acc4[d].w * inv);
        ((float4*)op)[d] = o;
    }
}

// ---------------------------------------------------------------------------
extern "C" void kernel_launch(void* const* d_in, const int* in_sizes, int n_in,
                              void* d_out, int out_size)
{
    const float* x  = (const float*)d_in[0];
    const float* Wq = (const float*)d_in[1];
    const float* Wk = (const float*)d_in[2];
    const float* Wv = (const float*)d_in[3];
    const float* Wo = (const float*)d_in[4];
    const float* bo = (const float*)d_in[5];
    float* out = (float*)d_out;

    cudaFuncSetAttribute(qkv_mma, cudaFuncAttributeMaxDynamicSharedMemorySize, GEMM_SMEM);
    cudaFuncSetAttribute(o_mma,   cudaFuncAttributeMaxDynamicSharedMemorySize, GEMM_SMEM);

    __nv_bfloat16 *xhi, *xlo, *wqh, *wql, *wkh, *wkl, *wvh, *wvl, *woh, *wol, *ahi, *alo;
    cudaGetSymbolAddress((void**)&xhi, g_xhi);  cudaGetSymbolAddress((void**)&xlo, g_xlo);
    cudaGetSymbolAddress((void**)&wqh, g_wqhi); cudaGetSymbolAddress((void**)&wql, g_wqlo);
    cudaGetSymbolAddress((void**)&wkh, g_wkhi); cudaGetSymbolAddress((void**)&wkl, g_wklo);
    cudaGetSymbolAddress((void**)&wvh, g_wvhi); cudaGetSymbolAddress((void**)&wvl, g_wvlo);
    cudaGetSymbolAddress((void**)&woh, g_wohi); cudaGetSymbolAddress((void**)&wol, g_wolo);
    cudaGetSymbolAddress((void**)&ahi, g_ahi);  cudaGetSymbolAddress((void**)&alo, g_alo);
    float* attn_f;
    cudaGetSymbolAddress((void**)&attn_f, g_attn);

    const int nX = MT * DM, nW = DM * DM;
    split_bf16<<<(nX + 255) / 256, 256>>>(x,  xhi, xlo, nX);
    split_bf16<<<(nW + 255) / 256, 256>>>(Wq, wqh, wql, nW);
    split_bf16<<<(nW + 255) / 256, 256>>>(Wk, wkh, wkl, nW);
    split_bf16<<<(nW + 255) / 256, 256>>>(Wv, wvh, wvl, nW);
    split_bf16<<<(nW + 255) / 256, 256>>>(Wo, woh, wol, nW);

    dim3 gqkv(DM / 128, MT / 128, 3);
    qkv_mma<<<gqkv, 512, GEMM_SMEM>>>();

    dim3 gattn(SS / 128, BB * NH);
    attn_kernel<<<gattn, 128>>>();

    split_bf16<<<(nX + 255) / 256, 256>>>(attn_f, ahi, alo, nX);

    dim3 go(DM / 128, MT / 128);
    o_mma<<<go, 512, GEMM_SMEM>>>(bo, out);
}

// round 5
// speedup vs baseline: 3.2088x; 2.3392x over previous
#include <cuda_runtime.h>
#include <cuda_bf16.h>
#include <cstdint>

// Problem constants
constexpr int DM = 1024;    // d_model
constexpr int NH = 16;      // heads
constexpr int DH = 64;      // head dim
constexpr int BB = 2;       // batch
constexpr int SS = 2048;    // seq len
constexpr int MT = BB * SS; // 4096 tokens

// softmax scale folded into Q, in log2 domain: 1/sqrt(64) * log2(e)
constexpr float QSCALE = 0.18033688011112042f;

// ---------------------------------------------------------------------------
// Scratch (device globals -- no allocations allowed)
// ---------------------------------------------------------------------------
__device__ __nv_bfloat16 g_xhi[MT * DM];
__device__ __nv_bfloat16 g_xlo[MT * DM];
__device__ __nv_bfloat16 g_wqhi[DM * DM];
__device__ __nv_bfloat16 g_wqlo[DM * DM];
__device__ __nv_bfloat16 g_wkhi[DM * DM];
__device__ __nv_bfloat16 g_wklo[DM * DM];
__device__ __nv_bfloat16 g_wvhi[DM * DM];
__device__ __nv_bfloat16 g_wvlo[DM * DM];
__device__ __nv_bfloat16 g_wohi[DM * DM];
__device__ __nv_bfloat16 g_wolo[DM * DM];
// projected q/k/v hi+lo planes (q pre-scaled by QSCALE)
__device__ __nv_bfloat16 g_qhi[MT * DM];
__device__ __nv_bfloat16 g_qlo[MT * DM];
__device__ __nv_bfloat16 g_khi[MT * DM];
__device__ __nv_bfloat16 g_klo[MT * DM];
__device__ __nv_bfloat16 g_vhi[MT * DM];
__device__ __nv_bfloat16 g_vlo[MT * DM];
// attention output hi+lo planes
__device__ __nv_bfloat16 g_ahi[MT * DM];
__device__ __nv_bfloat16 g_alo[MT * DM];

// ---------------------------------------------------------------------------
// PTX helpers (sm_80-baseline: cp.async, ldmatrix, mma.sync)
// ---------------------------------------------------------------------------
__device__ __forceinline__ uint32_t smem_to_u32(const void* p) {
    uint32_t a;
    asm("{ .reg .u64 t; cvta.to.shared.u64 t, %1; cvt.u32.u64 %0, t; }"
        : "=r"(a) : "l"(p));
    return a;
}
__device__ __forceinline__ void cp_async16(uint32_t dst, const void* src) {
    asm volatile("cp.async.cg.shared.global [%0], [%1], 16;"
                 :: "r"(dst), "l"(src) : "memory");
}
#define CP_COMMIT() asm volatile("cp.async.commit_group;" ::: "memory")
template <int N>
__device__ __forceinline__ void cp_wait() {
    asm volatile("cp.async.wait_group %0;" :: "n"(N) : "memory");
}
__device__ __forceinline__ void ldmx4(uint32_t (&r)[4], uint32_t addr) {
    asm volatile("ldmatrix.sync.aligned.m8n8.x4.shared.b16 {%0,%1,%2,%3}, [%4];"
                 : "=r"(r[0]), "=r"(r[1]), "=r"(r[2]), "=r"(r[3]) : "r"(addr));
}
__device__ __forceinline__ void ldmx4t(uint32_t (&r)[4], uint32_t addr) {
    asm volatile("ldmatrix.sync.aligned.m8n8.x4.trans.shared.b16 {%0,%1,%2,%3}, [%4];"
                 : "=r"(r[0]), "=r"(r[1]), "=r"(r[2]), "=r"(r[3]) : "r"(addr));
}
__device__ __forceinline__ void mma16816(float (&c)[4], const uint32_t (&a)[4],
                                         uint32_t b0, uint32_t b1) {
    asm volatile(
        "mma.sync.aligned.m16n8k16.row.col.f32.bf16.bf16.f32 "
        "{%0,%1,%2,%3}, {%4,%5,%6,%7}, {%8,%9}, {%0,%1,%2,%3};"
        : "+f"(c[0]), "+f"(c[1]), "+f"(c[2]), "+f"(c[3])
        : "r"(a[0]), "r"(a[1]), "r"(a[2]), "r"(a[3]), "r"(b0), "r"(b1));
}
__device__ __forceinline__ float ex2f(float x) {
    float r;
    asm("ex2.approx.ftz.f32 %0, %1;" : "=f"(r) : "f"(x));
    return r;
}
// pack (x,y) into bf16x2 hi reg and residual lo reg
__device__ __forceinline__ void split_pair(float x, float y,
                                           uint32_t& hi, uint32_t& lo) {
    __nv_bfloat162 h = __floats2bfloat162_rn(x, y);
    hi = *reinterpret_cast<uint32_t*>(&h);
    __nv_bfloat162 l = __floats2bfloat162_rn(x - __low2float(h), y - __high2float(h));
    lo = *reinterpret_cast<uint32_t*>(&l);
}

// GEMM tile swizzle (128-row x 32-bf16, 64B rows)
__device__ __forceinline__ uint32_t tile_off(int row, int kg) {
    return (uint32_t)(row * 64 + (((kg ^ ((row >> 1) & 3)) & 3) << 4));
}
// Attention tile swizzle (rows of 64 bf16 = 128B, 8 chunks of 16B)
__device__ __forceinline__ uint32_t atile_off(int row, int c) {
    return (uint32_t)(row * 128 + (((c ^ (row & 7)) & 7) << 4));
}

// ---------------------------------------------------------------------------
// hi/lo bf16 split conversion (inputs only)
// ---------------------------------------------------------------------------
__global__ __launch_bounds__(256) void split_bf16(const float* __restrict__ src,
                                                  __nv_bfloat16* __restrict__ hi,
                                                  __nv_bfloat16* __restrict__ lo, int n) {
    int i = blockIdx.x * 256 + threadIdx.x;
    if (i < n) {
        float x = src[i];
        __nv_bfloat16 h = __float2bfloat16(x);
        hi[i] = h;
        lo[i] = __float2bfloat16(x - __bfloat162float(h));
    }
}

// ---------------------------------------------------------------------------
// bf16x3 tensor-core GEMM: 128x128 tile, K=1024 chunked by 32, cp.async x2.
// 512 threads = 16 warps (4m x 4n), warp tile 32x32.
// Epilogue either fp32+bias (Yf32) or hi/lo bf16 split with scale (Yhi/Ylo).
// ---------------------------------------------------------------------------
constexpr int GEMM_SMEM = 2 * 32768;

__device__ __forceinline__ void stage_load(
    uint32_t sbase, int st,
    const __nv_bfloat16* __restrict__ Ah, const __nv_bfloat16* __restrict__ Al,
    const __nv_bfloat16* __restrict__ Bh, const __nv_bfloat16* __restrict__ Bl,
    int bm, int bn, int k0, int lrow, int lkg, uint32_t ldst)
{
    const uint32_t base = sbase + st * 32768 + ldst;
    const __nv_bfloat16* planes[4] = {Ah, Al, Bh, Bl};
#pragma unroll
    for (int pl = 0; pl < 4; pl++) {
        int rowbase = (pl < 2) ? bm : bn;
        const __nv_bfloat16* src =
            planes[pl] + (size_t)(rowbase + lrow) * 1024 + k0 + lkg * 8;
        cp_async16(base + pl * 8192, src);
    }
}

__device__ __forceinline__ void mma_gemm_body(
    const __nv_bfloat16* __restrict__ Ah, const __nv_bfloat16* __restrict__ Al,
    const __nv_bfloat16* __restrict__ Bh, const __nv_bfloat16* __restrict__ Bl,
    float* __restrict__ Yf32, const float* __restrict__ bias,
    __nv_bfloat16* __restrict__ Yhi, __nv_bfloat16* __restrict__ Ylo, float oscale)
{
    extern __shared__ char smem[];
    const uint32_t sbase = smem_to_u32(smem);
    const int tid  = threadIdx.x;
    const int wid  = tid >> 5;
    const int lane = tid & 31;
    const int m_base = (wid & 3) * 32;
    const int n_base = (wid >> 2) * 32;
    const int bm = blockIdx.y * 128;
    const int bn = blockIdx.x * 128;

    const int lrow = tid >> 2;
    const int lkg  = tid & 3;
    const uint32_t ldst = tile_off(lrow, lkg);

    float acc[2][4][4];
#pragma unroll
    for (int mt = 0; mt < 2; mt++)
#pragma unroll
        for (int nt = 0; nt < 4; nt++)
#pragma unroll
            for (int i = 0; i < 4; i++) acc[mt][nt][i] = 0.f;

    stage_load(sbase, 0, Ah, Al, Bh, Bl, bm, bn, 0, lrow, lkg, ldst);
    CP_COMMIT();

    for (int kc = 0; kc < 32; kc++) {
        if (kc < 31) {
            stage_load(sbase, (kc + 1) & 1, Ah, Al, Bh, Bl, bm, bn,
                       (kc + 1) * 32, lrow, lkg, ldst);
            CP_COMMIT();
            cp_wait<1>();
        } else {
            cp_wait<0>();
        }
        __syncthreads();

        const uint32_t st = sbase + (kc & 1) * 32768;
#pragma unroll
        for (int s = 0; s < 2; s++) {
            uint32_t ah[2][4], al[2][4], bh[2][4], bl[2][4];
            {
                int r   = lane & 7;
                int sel = lane >> 3;
                int kg  = 2 * s + (sel >> 1);
#pragma unroll
                for (int mt = 0; mt < 2; mt++) {
                    int row = m_base + mt * 16 + r + ((sel & 1) << 3);
                    uint32_t off = tile_off(row, kg);
                    ldmx4(ah[mt], st + off);
                    ldmx4(al[mt], st + 8192 + off);
                }
            }
            {
                int r  = lane & 7;
                int kg = 2 * s + ((lane >> 3) & 1);
#pragma unroll
                for (int ng = 0; ng < 2; ng++) {
                    int row = n_base + ng * 16 + r + ((lane >> 4) << 3);
                    uint32_t off = tile_off(row, kg);
                    ldmx4(bh[ng], st + 16384 + off);
                    ldmx4(bl[ng], st + 24576 + off);
                }
            }
#pragma unroll
            for (int mt = 0; mt < 2; mt++)
#pragma unroll
                for (int nt = 0; nt < 4; nt++) {
                    int g = nt >> 1, o = (nt & 1) * 2;
                    mma16816(acc[mt][nt], ah[mt], bh[g][o], bh[g][o + 1]);
                    mma16816(acc[mt][nt], ah[mt], bl[g][o], bl[g][o + 1]);
                    mma16816(acc[mt][nt], al[mt], bh[g][o], bh[g][o + 1]);
                }
        }
        __syncthreads();
    }

    const int gid = lane >> 2;
    const int tig = lane & 3;
#pragma unroll
    for (int mt = 0; mt < 2; mt++) {
#pragma unroll
        for (int nt = 0; nt < 4; nt++) {
            int row0 = bm + m_base + mt * 16 + gid;
            int col0 = bn + n_base + nt * 8 + tig * 2;
            if (Yf32) {
                float b0 = bias ? bias[col0]     : 0.f;
                float b1 = bias ? bias[col0 + 1] : 0.f;
                float2 v0 = make_float2(acc[mt][nt][0] + b0, acc[mt][nt][1] + b1);
                float2 v1 = make_float2(acc[mt][nt][2] + b0, acc[mt][nt][3] + b1);
                *(float2*)(Yf32 + (size_t)row0 * 1024 + col0)       = v0;
                *(float2*)(Yf32 + (size_t)(row0 + 8) * 1024 + col0) = v1;
            } else {
                uint32_t h0, l0, h1, l1;
                split_pair(acc[mt][nt][0] * oscale, acc[mt][nt][1] * oscale, h0, l0);
                split_pair(acc[mt][nt][2] * oscale, acc[mt][nt][3] * oscale, h1, l1);
                *(uint32_t*)(Yhi + (size_t)row0 * 1024 + col0)       = h0;
                *(uint32_t*)(Ylo + (size_t)row0 * 1024 + col0)       = l0;
                *(uint32_t*)(Yhi + (size_t)(row0 + 8) * 1024 + col0) = h1;
                *(uint32_t*)(Ylo + (size_t)(row0 + 8) * 1024 + col0) = l1;
            }
        }
    }
}

__global__ __launch_bounds__(512) void qkv_mma() {
    const __nv_bfloat16 *Bh, *Bl;
    __nv_bfloat16 *Yh, *Yl;
    float sc;
    if (blockIdx.z == 0)      { Bh = g_wqhi; Bl = g_wqlo; Yh = g_qhi; Yl = g_qlo; sc = QSCALE; }
    else if (blockIdx.z == 1) { Bh = g_wkhi; Bl = g_wklo; Yh = g_khi; Yl = g_klo; sc = 1.f; }
    else                      { Bh = g_wvhi; Bl = g_wvlo; Yh = g_vhi; Yl = g_vlo; sc = 1.f; }
    mma_gemm_body(g_xhi, g_xlo, Bh, Bl, nullptr, nullptr, Yh, Yl, sc);
}

__global__ __launch_bounds__(512) void o_mma(const float* __restrict__ bo,
                                             float* __restrict__ out) {
    mma_gemm_body(g_ahi, g_alo, g_wohi, g_wolo, out, bo, nullptr, nullptr, 1.f);
}

// ---------------------------------------------------------------------------
// Tensor-core causal flash attention, bf16x3.
// grid = (S/128, B*H), 256 threads (8 warps, warp = 16 q rows).
// Q resident in smem (hi+lo, 32KB); KV tiles of 64 rows double-buffered.
// smem: Qh@0, Ql@16384; stage s @ 32768+s*32768: Kh+0, Kl+8192, Vh+16384, Vl+24576
// ---------------------------------------------------------------------------
constexpr int ATTN_SMEM = 32768 + 2 * 32768;  // 98304

__device__ __forceinline__ void attn_load_kv(uint32_t sb, int stage, int kv0,
                                             size_t headoff, int tid) {
#pragma unroll
    for (int i = 0; i < 8; i++) {
        int idx = tid + 256 * i;        // 0..2047
        int pl  = idx >> 9;             // 0..3 : Kh,Kl,Vh,Vl
        int ci  = idx & 511;
        int r   = ci >> 3;
        int c   = ci & 7;
        const __nv_bfloat16* base =
            (pl == 0) ? g_khi : (pl == 1) ? g_klo : (pl == 2) ? g_vhi : g_vlo;
        const __nv_bfloat16* src = base + headoff + (size_t)(kv0 + r) * DM + c * 8;
        cp_async16(sb + 32768 + stage * 32768 + pl * 8192 + atile_off(r, c), src);
    }
    CP_COMMIT();
}

__global__ __launch_bounds__(256) void attn_mma() {
    extern __shared__ char smem[];
    const uint32_t sb = smem_to_u32(smem);
    const int tid  = threadIdx.x;
    const int wid  = tid >> 5;
    const int lane = tid & 31;
    const int gid  = lane >> 2;
    const int tig  = lane & 3;
    const int bx   = blockIdx.x;
    const int bh   = blockIdx.y;
    const int b    = bh >> 4;
    const int h    = bh & 15;
    const int qb   = bx * 128;
    const int qw   = wid * 16;  // warp's q-row base within block
    const size_t headoff = (size_t)(b * SS) * DM + h * 64;

    // Q load (once): 2 planes x 128 rows x 8 chunks = 2048 chunks
#pragma unroll
    for (int i = 0; i < 8; i++) {
        int idx = tid + 256 * i;
        int pl  = idx >> 10;
        int ci  = idx & 1023;
        int r   = ci >> 3;
        int c   = ci & 7;
        const __nv_bfloat16* src =
            (pl ? g_qlo : g_qhi) + headoff + (size_t)(qb + r) * DM + c * 8;
        cp_async16(sb + pl * 16384 + atile_off(r, c), src);
    }
    CP_COMMIT();

    float o[8][4];
#pragma unroll
    for (int nt = 0; nt < 8; nt++)
#pragma unroll
        for (int i = 0; i < 4; i++) o[nt][i] = 0.f;
    float m0 = -1e30f, m1 = -1e30f, l0 = 0.f, l1 = 0.f;

    const int ntiles = 2 * bx + 2;
    attn_load_kv(sb, 0, 0, headoff, tid);

    for (int t = 0; t < ntiles; t++) {
        if (t + 1 < ntiles) {
            attn_load_kv(sb, (t + 1) & 1, (t + 1) * 64, headoff, tid);
            cp_wait<1>();
        } else {
            cp_wait<0>();
        }
        __syncthreads();
        const uint32_t kst = sb + 32768 + (t & 1) * 32768;

        // ---- S = Qs * K^T (3 passes, fp32 acc, already in log2 units) ----
        float sf[8][4];
#pragma unroll
        for (int jt = 0; jt < 8; jt++)
#pragma unroll
            for (int i = 0; i < 4; i++) sf[jt][i] = 0.f;

#pragma unroll
        for (int kc = 0; kc < 4; kc++) {
            uint32_t qh[4], ql[4];
            {
                int r = lane & 7, sel = lane >> 3;
                int row = qw + r + ((sel & 1) << 3);
                int c = kc * 2 + (sel >> 1);
                uint32_t off = atile_off(row, c);
                ldmx4(qh, sb + off);
                ldmx4(ql, sb + 16384 + off);
            }
#pragma unroll
            for (int g2 = 0; g2 < 4; g2++) {
                uint32_t kh[4], kl[4];
                {
                    int r = lane & 7;
                    int row = g2 * 16 + r + ((lane >> 4) << 3);
                    int c = kc * 2 + ((lane >> 3) & 1);
                    uint32_t off = atile_off(row, c);
                    ldmx4(kh, kst + off);
                    ldmx4(kl, kst + 8192 + off);
                }
#pragma unroll
                for (int jj = 0; jj < 2; jj++) {
                    int jt = g2 * 2 + jj, o2 = jj * 2;
                    mma16816(sf[jt], qh, kh[o2], kh[o2 + 1]);
                    mma16816(sf[jt], qh, kl[o2], kl[o2 + 1]);
                    mma16816(sf[jt], ql, kh[o2], kh[o2 + 1]);
                }
            }
        }

        // ---- causal mask (only the two diagonal tiles) ----
        if (t >= 2 * bx) {
            const int kv0 = t * 64;
            const int r0 = qb + qw + gid, r1 = r0 + 8;
#pragma unroll
            for (int jt = 0; jt < 8; jt++) {
                int col = kv0 + jt * 8 + tig * 2;
                if (col     > r0) sf[jt][0] = -1e30f;
                if (col + 1 > r0) sf[jt][1] = -1e30f;
                if (col     > r1) sf[jt][2] = -1e30f;
                if (col + 1 > r1) sf[jt][3] = -1e30f;
            }
        }

        // ---- online softmax (base-2) ----
        float tm0 = -1e30f, tm1 = -1e30f;
#pragma unroll
        for (int jt = 0; jt < 8; jt++) {
            tm0 = fmaxf(tm0, fmaxf(sf[jt][0], sf[jt][1]));
            tm1 = fmaxf(tm1, fmaxf(sf[jt][2], sf[jt][3]));
        }
        tm0 = fmaxf(tm0, __shfl_xor_sync(0xFFFFFFFFu, tm0, 1));
        tm0 = fmaxf(tm0, __shfl_xor_sync(0xFFFFFFFFu, tm0, 2));
        tm1 = fmaxf(tm1, __shfl_xor_sync(0xFFFFFFFFu, tm1, 1));
        tm1 = fmaxf(tm1, __shfl_xor_sync(0xFFFFFFFFu, tm1, 2));

        float mn0 = fmaxf(fmaxf(m0, tm0), -1e4f);
        float mn1 = fmaxf(fmaxf(m1, tm1), -1e4f);
        float c0 = ex2f(m0 - mn0);
        float c1 = ex2f(m1 - mn1);
        m0 = mn0; m1 = mn1;

        float rs0 = 0.f, rs1 = 0.f;
#pragma unroll
        for (int jt = 0; jt < 8; jt++) {
            sf[jt][0] = ex2f(sf[jt][0] - mn0);
            sf[jt][1] = ex2f(sf[jt][1] - mn0);
            sf[jt][2] = ex2f(sf[jt][2] - mn1);
            sf[jt][3] = ex2f(sf[jt][3] - mn1);
            rs0 += sf[jt][0] + sf[jt][1];
            rs1 += sf[jt][2] + sf[jt][3];
        }
        rs0 += __shfl_xor_sync(0xFFFFFFFFu, rs0, 1);
        rs0 += __shfl_xor_sync(0xFFFFFFFFu, rs0, 2);
        rs1 += __shfl_xor_sync(0xFFFFFFFFu, rs1, 1);
        rs1 += __shfl_xor_sync(0xFFFFFFFFu, rs1, 2);
        l0 = l0 * c0 + rs0;
        l1 = l1 * c1 + rs1;

#pragma unroll
        for (int nt = 0; nt < 8; nt++) {
            o[nt][0] *= c0; o[nt][1] *= c0;
            o[nt][2] *= c1; o[nt][3] *= c1;
        }

        // ---- O += P * V (3 passes); P packed from sf regs ----
#pragma unroll
        for (int kc = 0; kc < 4; kc++) {
            uint32_t ph[4], pl4[4];
#pragma unroll
            for (int s = 0; s < 4; s++) {
                int jt = 2 * kc + (s >> 1);
                split_pair(sf[jt][(s & 1) * 2], sf[jt][(s & 1) * 2 + 1],
                           ph[s], pl4[s]);
            }
#pragma unroll
            for (int dg = 0; dg < 4; dg++) {
                uint32_t vh[4], vl[4];
                {
                    int r = lane & 7;
                    int row = kc * 16 + r + (((lane >> 3) & 1) << 3);
                    int c = dg * 2 + (lane >> 4);
                    uint32_t off = atile_off(row, c);
                    ldmx4t(vh, kst + 16384 + off);
                    ldmx4t(vl, kst + 24576 + off);
                }
#pragma unroll
                for (int jj = 0; jj < 2; jj++) {
                    int nt = dg * 2 + jj, o2 = jj * 2;
                    mma16816(o[nt], ph, vh[o2], vh[o2 + 1]);
                    mma16816(o[nt], ph, vl[o2], vl[o2 + 1]);
                    mma16816(o[nt], pl4, vh[o2], vh[o2 + 1]);
                }
            }
        }
        __syncthreads();   // all warps done with stage t before its buffer reload
    }

    // ---- epilogue: O / l -> split hi/lo bf16 planes ----
    const float inv0 = 1.f / l0;
    const float inv1 = 1.f / l1;
    const size_t tok0 = (size_t)(b * SS + qb + qw + gid) * DM;
#pragma unroll
    for (int nt = 0; nt < 8; nt++) {
        int col = h * 64 + nt * 8 + tig * 2;
        uint32_t h0, lo0, h1, lo1;
        split_pair(o[nt][0] * inv0, o[nt][1] * inv0, h0, lo0);
        split_pair(o[nt][2] * inv1, o[nt][3] * inv1, h1, lo1);
        *(uint32_t*)(g_ahi + tok0 + col)            = h0;
        *(uint32_t*)(g_alo + tok0 + col)            = lo0;
        *(uint32_t*)(g_ahi + tok0 + 8 * DM + col)   = h1;
        *(uint32_t*)(g_alo + tok0 + 8 * DM + col)   = lo1;
    }
}

// ---------------------------------------------------------------------------
extern "C" void kernel_launch(void* const* d_in, const int* in_sizes, int n_in,
                              void* d_out, int out_size)
{
    const float* x  = (const float*)d_in[0];
    const float* Wq = (const float*)d_in[1];
    const float* Wk = (const float*)d_in[2];
    const float* Wv = (const float*)d_in[3];
    const float* Wo = (const float*)d_in[4];
    const float* bo = (const float*)d_in[5];
    float* out = (float*)d_out;

    cudaFuncSetAttribute(qkv_mma,  cudaFuncAttributeMaxDynamicSharedMemorySize, GEMM_SMEM);
    cudaFuncSetAttribute(o_mma,    cudaFuncAttributeMaxDynamicSharedMemorySize, GEMM_SMEM);
    cudaFuncSetAttribute(attn_mma, cudaFuncAttributeMaxDynamicSharedMemorySize, ATTN_SMEM);

    __nv_bfloat16 *xhi, *xlo, *wqh, *wql, *wkh, *wkl, *wvh, *wvl, *woh, *wol;
    cudaGetSymbolAddress((void**)&xhi, g_xhi);  cudaGetSymbolAddress((void**)&xlo, g_xlo);
    cudaGetSymbolAddress((void**)&wqh, g_wqhi); cudaGetSymbolAddress((void**)&wql, g_wqlo);
    cudaGetSymbolAddress((void**)&wkh, g_wkhi); cudaGetSymbolAddress((void**)&wkl, g_wklo);
    cudaGetSymbolAddress((void**)&wvh, g_wvhi); cudaGetSymbolAddress((void**)&wvl, g_wvlo);
    cudaGetSymbolAddress((void**)&woh, g_wohi); cudaGetSymbolAddress((void**)&wol, g_wolo);

    const int nX = MT * DM, nW = DM * DM;
    split_bf16<<<(nX + 255) / 256, 256>>>(x,  xhi, xlo, nX);
    split_bf16<<<(nW + 255) / 256, 256>>>(Wq, wqh, wql, nW);
    split_bf16<<<(nW + 255) / 256, 256>>>(Wk, wkh, wkl, nW);
    split_bf16<<<(nW + 255) / 256, 256>>>(Wv, wvh, wvl, nW);
    split_bf16<<<(nW + 255) / 256, 256>>>(Wo, woh, wol, nW);

    dim3 gqkv(DM / 128, MT / 128, 3);
    qkv_mma<<<gqkv, 512, GEMM_SMEM>>>();

    dim3 gattn(SS / 128, BB * NH);
    attn_mma<<<gattn, 256, ATTN_SMEM>>>();

    dim3 go(DM / 128, MT / 128);
    o_mma<<<go, 512, GEMM_SMEM>>>(bo, out);
}

// round 6
// speedup vs baseline: 4.2115x; 1.3125x over previous
#include <cuda_runtime.h>
#include <cuda_fp16.h>
#include <cstdint>

// Problem constants
constexpr int DM = 1024;    // d_model
constexpr int NH = 16;      // heads
constexpr int DH = 64;      // head dim
constexpr int BB = 2;       // batch
constexpr int SS = 2048;    // seq len
constexpr int MT = BB * SS; // 4096 tokens

// softmax scale folded into Q, in log2 domain: 1/sqrt(64) * log2(e)
constexpr float QSCALE = 0.18033688011112042f;

// ---------------------------------------------------------------------------
// Scratch (device globals -- no allocations allowed)
// ---------------------------------------------------------------------------
__device__ __half g_xh[MT * DM];                      // activations: hi only
__device__ __half g_wqhi[DM * DM], g_wqlo[DM * DM];   // weights: hi + lo
__device__ __half g_wkhi[DM * DM], g_wklo[DM * DM];
__device__ __half g_wvhi[DM * DM], g_wvlo[DM * DM];
__device__ __half g_wohi[DM * DM], g_wolo[DM * DM];
__device__ __half g_qh[MT * DM];                      // q: hi only (pre-scaled)
__device__ __half g_khi[MT * DM], g_klo[MT * DM];     // k: hi + lo
__device__ __half g_vhi[MT * DM], g_vlo[MT * DM];     // v: hi + lo
__device__ __half g_ah[MT * DM];                      // attn out: hi only

// ---------------------------------------------------------------------------
// PTX helpers (sm_80-baseline: cp.async, ldmatrix, mma.sync)
// ---------------------------------------------------------------------------
__device__ __forceinline__ uint32_t smem_to_u32(const void* p) {
    uint32_t a;
    asm("{ .reg .u64 t; cvta.to.shared.u64 t, %1; cvt.u32.u64 %0, t; }"
        : "=r"(a) : "l"(p));
    return a;
}
__device__ __forceinline__ void cp_async16(uint32_t dst, const void* src) {
    asm volatile("cp.async.cg.shared.global [%0], [%1], 16;"
                 :: "r"(dst), "l"(src) : "memory");
}
#define CP_COMMIT() asm volatile("cp.async.commit_group;" ::: "memory")
template <int N>
__device__ __forceinline__ void cp_wait() {
    asm volatile("cp.async.wait_group %0;" :: "n"(N) : "memory");
}
__device__ __forceinline__ void ldmx4(uint32_t (&r)[4], uint32_t addr) {
    asm volatile("ldmatrix.sync.aligned.m8n8.x4.shared.b16 {%0,%1,%2,%3}, [%4];"
                 : "=r"(r[0]), "=r"(r[1]), "=r"(r[2]), "=r"(r[3]) : "r"(addr));
}
__device__ __forceinline__ void ldmx4t(uint32_t (&r)[4], uint32_t addr) {
    asm volatile("ldmatrix.sync.aligned.m8n8.x4.trans.shared.b16 {%0,%1,%2,%3}, [%4];"
                 : "=r"(r[0]), "=r"(r[1]), "=r"(r[2]), "=r"(r[3]) : "r"(addr));
}
__device__ __forceinline__ void mma16816(float (&c)[4], const uint32_t (&a)[4],
                                         uint32_t b0, uint32_t b1) {
    asm volatile(
        "mma.sync.aligned.m16n8k16.row.col.f32.f16.f16.f32 "
        "{%0,%1,%2,%3}, {%4,%5,%6,%7}, {%8,%9}, {%0,%1,%2,%3};"
        : "+f"(c[0]), "+f"(c[1]), "+f"(c[2]), "+f"(c[3])
        : "r"(a[0]), "r"(a[1]), "r"(a[2]), "r"(a[3]), "r"(b0), "r"(b1));
}
__device__ __forceinline__ float ex2f(float x) {
    float r;
    asm("ex2.approx.ftz.f32 %0, %1;" : "=f"(r) : "f"(x));
    return r;
}
__device__ __forceinline__ uint32_t pack_h2(float x, float y) {
    __half2 h = __floats2half2_rn(x, y);
    return *reinterpret_cast<uint32_t*>(&h);
}
__device__ __forceinline__ void split_pair_h(float x, float y,
                                             uint32_t& hi, uint32_t& lo) {
    __half2 h = __floats2half2_rn(x, y);
    hi = *reinterpret_cast<uint32_t*>(&h);
    __half2 l = __floats2half2_rn(x - __low2float(h), y - __high2float(h));
    lo = *reinterpret_cast<uint32_t*>(&l);
}

// GEMM tile swizzle (128-row x 32-half, 64B rows)
__device__ __forceinline__ uint32_t tile_off(int row, int kg) {
    return (uint32_t)(row * 64 + (((kg ^ ((row >> 1) & 3)) & 3) << 4));
}
// Attention tile swizzle (rows of 64 half = 128B, 8 chunks of 16B)
__device__ __forceinline__ uint32_t atile_off(int row, int c) {
    return (uint32_t)(row * 128 + (((c ^ (row & 7)) & 7) << 4));
}

// ---------------------------------------------------------------------------
// Input conversions
// ---------------------------------------------------------------------------
__global__ __launch_bounds__(256) void cvt_x(const float* __restrict__ src,
                                             __half* __restrict__ dst, int n) {
    int i = blockIdx.x * 256 + threadIdx.x;
    if (i < n) dst[i] = __float2half_rn(src[i]);
}

__global__ __launch_bounds__(256) void split_w4(
    const float* __restrict__ Wq, const float* __restrict__ Wk,
    const float* __restrict__ Wv, const float* __restrict__ Wo) {
    const int w = blockIdx.y;
    const float* src = (w == 0) ? Wq : (w == 1) ? Wk : (w == 2) ? Wv : Wo;
    __half* hi = (w == 0) ? g_wqhi : (w == 1) ? g_wkhi : (w == 2) ? g_wvhi : g_wohi;
    __half* lo = (w == 0) ? g_wqlo : (w == 1) ? g_wklo : (w == 2) ? g_wvlo : g_wolo;
    int i = blockIdx.x * 256 + threadIdx.x;
    if (i < DM * DM) {
        float x = src[i];
        __half h = __float2half_rn(x);
        hi[i] = h;
        lo[i] = __float2half_rn(x - __half2float(h));
    }
}

// ---------------------------------------------------------------------------
// fp16x2 tensor-core GEMM: Y = A @ B^T;  A ~ Ah (hi only), B ~ Bh + Bl.
// Y = Ah*Bh + Ah*Bl, fp32 accum. 128x128 tile, K chunked by 32, 3-stage
// cp.async. 512 threads = 16 warps (4m x 4n), warp tile 32x32.
// Stage: Ah(8KB) | Bh(8KB) | Bl(8KB) = 24KB; 3 stages.
// ---------------------------------------------------------------------------
constexpr int GSTAGE = 24576;
constexpr int GEMM_SMEM = 3 * GSTAGE;   // 73728

__device__ __forceinline__ void stage_load(
    uint32_t sbase, int st, const __half* __restrict__ Ah,
    const __half* __restrict__ Bh, const __half* __restrict__ Bl,
    int bm, int bn, int k0, int lrow, int lkg, uint32_t ldst)
{
    const uint32_t base = sbase + st * GSTAGE + ldst;
    cp_async16(base,         Ah + (size_t)(bm + lrow) * 1024 + k0 + lkg * 8);
    cp_async16(base + 8192,  Bh + (size_t)(bn + lrow) * 1024 + k0 + lkg * 8);
    cp_async16(base + 16384, Bl + (size_t)(bn + lrow) * 1024 + k0 + lkg * 8);
}

__device__ __forceinline__ void mma_gemm_body(
    const __half* __restrict__ Ah,
    const __half* __restrict__ Bh, const __half* __restrict__ Bl,
    float* __restrict__ Yf32, const float* __restrict__ bias,
    __half* __restrict__ Yhi, __half* __restrict__ Ylo, float oscale)
{
    extern __shared__ char smem[];
    const uint32_t sbase = smem_to_u32(smem);
    const int tid  = threadIdx.x;
    const int wid  = tid >> 5;
    const int lane = tid & 31;
    const int m_base = (wid & 3) * 32;
    const int n_base = (wid >> 2) * 32;
    const int bm = blockIdx.y * 128;
    const int bn = blockIdx.x * 128;

    const int lrow = tid >> 2;
    const int lkg  = tid & 3;
    const uint32_t ldst = tile_off(lrow, lkg);

    float acc[2][4][4];
#pragma unroll
    for (int mt = 0; mt < 2; mt++)
#pragma unroll
        for (int nt = 0; nt < 4; nt++)
#pragma unroll
            for (int i = 0; i < 4; i++) acc[mt][nt][i] = 0.f;

    stage_load(sbase, 0, Ah, Bh, Bl, bm, bn, 0, lrow, lkg, ldst);
    CP_COMMIT();
    stage_load(sbase, 1, Ah, Bh, Bl, bm, bn, 32, lrow, lkg, ldst);
    CP_COMMIT();

    int st_idx = 0;
    for (int kc = 0; kc < 32; kc++) {
        if (kc < 30) {
            int ns = (st_idx + 2) % 3;
            stage_load(sbase, ns, Ah, Bh, Bl, bm, bn, (kc + 2) * 32,
                       lrow, lkg, ldst);
            CP_COMMIT();
            cp_wait<2>();
        } else if (kc == 30) {
            cp_wait<1>();
        } else {
            cp_wait<0>();
        }
        __syncthreads();

        const uint32_t st = sbase + st_idx * GSTAGE;
#pragma unroll
        for (int s = 0; s < 2; s++) {
            uint32_t ah[2][4], bh[2][4], bl[2][4];
            {
                int r   = lane & 7;
                int sel = lane >> 3;
                int kg  = 2 * s + (sel >> 1);
#pragma unroll
                for (int mt = 0; mt < 2; mt++) {
                    int row = m_base + mt * 16 + r + ((sel & 1) << 3);
                    ldmx4(ah[mt], st + tile_off(row, kg));
                }
            }
            {
                int r  = lane & 7;
                int kg = 2 * s + ((lane >> 3) & 1);
#pragma unroll
                for (int ng = 0; ng < 2; ng++) {
                    int row = n_base + ng * 16 + r + ((lane >> 4) << 3);
                    uint32_t off = tile_off(row, kg);
                    ldmx4(bh[ng], st + 8192  + off);
                    ldmx4(bl[ng], st + 16384 + off);
                }
            }
#pragma unroll
            for (int mt = 0; mt < 2; mt++)
#pragma unroll
                for (int nt = 0; nt < 4; nt++) {
                    int g = nt >> 1, o = (nt & 1) * 2;
                    mma16816(acc[mt][nt], ah[mt], bh[g][o], bh[g][o + 1]);
                    mma16816(acc[mt][nt], ah[mt], bl[g][o], bl[g][o + 1]);
                }
        }
        __syncthreads();
        st_idx = (st_idx + 1) % 3;
    }

    const int gid = lane >> 2;
    const int tig = lane & 3;
#pragma unroll
    for (int mt = 0; mt < 2; mt++) {
#pragma unroll
        for (int nt = 0; nt < 4; nt++) {
            int row0 = bm + m_base + mt * 16 + gid;
            int col0 = bn + n_base + nt * 8 + tig * 2;
            if (Yf32) {
                float b0 = bias ? bias[col0]     : 0.f;
                float b1 = bias ? bias[col0 + 1] : 0.f;
                float2 v0 = make_float2(acc[mt][nt][0] + b0, acc[mt][nt][1] + b1);
                float2 v1 = make_float2(acc[mt][nt][2] + b0, acc[mt][nt][3] + b1);
                *(float2*)(Yf32 + (size_t)row0 * 1024 + col0)       = v0;
                *(float2*)(Yf32 + (size_t)(row0 + 8) * 1024 + col0) = v1;
            } else if (Ylo) {
                uint32_t h0, l0, h1, l1;
                split_pair_h(acc[mt][nt][0] * oscale, acc[mt][nt][1] * oscale, h0, l0);
                split_pair_h(acc[mt][nt][2] * oscale, acc[mt][nt][3] * oscale, h1, l1);
                *(uint32_t*)(Yhi + (size_t)row0 * 1024 + col0)       = h0;
                *(uint32_t*)(Ylo + (size_t)row0 * 1024 + col0)       = l0;
                *(uint32_t*)(Yhi + (size_t)(row0 + 8) * 1024 + col0) = h1;
                *(uint32_t*)(Ylo + (size_t)(row0 + 8) * 1024 + col0) = l1;
            } else {
                uint32_t h0 = pack_h2(acc[mt][nt][0] * oscale, acc[mt][nt][1] * oscale);
                uint32_t h1 = pack_h2(acc[mt][nt][2] * oscale, acc[mt][nt][3] * oscale);
                *(uint32_t*)(Yhi + (size_t)row0 * 1024 + col0)       = h0;
                *(uint32_t*)(Yhi + (size_t)(row0 + 8) * 1024 + col0) = h1;
            }
        }
    }
}

__global__ __launch_bounds__(512) void qkv_mma() {
    if (blockIdx.z == 0)
        mma_gemm_body(g_xh, g_wqhi, g_wqlo, nullptr, nullptr, g_qh, nullptr, QSCALE);
    else if (blockIdx.z == 1)
        mma_gemm_body(g_xh, g_wkhi, g_wklo, nullptr, nullptr, g_khi, g_klo, 1.f);
    else
        mma_gemm_body(g_xh, g_wvhi, g_wvlo, nullptr, nullptr, g_vhi, g_vlo, 1.f);
}

__global__ __launch_bounds__(512) void o_mma(const float* __restrict__ bo,
                                             float* __restrict__ out) {
    mma_gemm_body(g_ah, g_wohi, g_wolo, out, bo, nullptr, nullptr, 1.f);
}

// ---------------------------------------------------------------------------
// Tensor-core causal flash attention, fp16x2.
// grid = (S/128, B*H), 256 threads (8 warps, warp = 16 q rows).
// Q hi resident in smem (16KB); KV stage (Kh,Kl,Vh,Vl = 32KB) x2.
// ---------------------------------------------------------------------------
constexpr int ATTN_SMEM = 16384 + 2 * 32768;  // 81920

__device__ __forceinline__ void attn_load_kv(uint32_t sb, int stage, int kv0,
                                             size_t headoff, int tid) {
#pragma unroll
    for (int i = 0; i < 8; i++) {
        int idx = tid + 256 * i;        // 0..2047
        int pl  = idx >> 9;             // Kh,Kl,Vh,Vl
        int ci  = idx & 511;
        int r   = ci >> 3;
        int c   = ci & 7;
        const __half* base =
            (pl == 0) ? g_khi : (pl == 1) ? g_klo : (pl == 2) ? g_vhi : g_vlo;
        cp_async16(sb + 16384 + stage * 32768 + pl * 8192 + atile_off(r, c),
                   base + headoff + (size_t)(kv0 + r) * DM + c * 8);
    }
    CP_COMMIT();
}

__global__ __launch_bounds__(256) void attn_mma() {
    extern __shared__ char smem[];
    const uint32_t sb = smem_to_u32(smem);
    const int tid  = threadIdx.x;
    const int wid  = tid >> 5;
    const int lane = tid & 31;
    const int gid  = lane >> 2;
    const int tig  = lane & 3;
    const int bx   = blockIdx.x;
    const int bh   = blockIdx.y;
    const int b    = bh >> 4;
    const int h    = bh & 15;
    const int qb   = bx * 128;
    const int qw   = wid * 16;
    const size_t headoff = (size_t)(b * SS) * DM + h * 64;

    // Q hi load (once): 128 rows x 8 chunks = 1024 chunks
#pragma unroll
    for (int i = 0; i < 4; i++) {
        int idx = tid + 256 * i;
        int r   = idx >> 3;
        int c   = idx & 7;
        cp_async16(sb + atile_off(r, c),
                   g_qh + headoff + (size_t)(qb + r) * DM + c * 8);
    }
    CP_COMMIT();

    float o[8][4];
#pragma unroll
    for (int nt = 0; nt < 8; nt++)
#pragma unroll
        for (int i = 0; i < 4; i++) o[nt][i] = 0.f;
    float m0 = -1e30f, m1 = -1e30f, l0 = 0.f, l1 = 0.f;

    const int ntiles = 2 * bx + 2;
    attn_load_kv(sb, 0, 0, headoff, tid);

    for (int t = 0; t < ntiles; t++) {
        if (t + 1 < ntiles) {
            attn_load_kv(sb, (t + 1) & 1, (t + 1) * 64, headoff, tid);
            cp_wait<1>();
        } else {
            cp_wait<0>();
        }
        __syncthreads();
        const uint32_t kst = sb + 16384 + (t & 1) * 32768;

        // ---- S = Qh * (Kh + Kl)^T  (log2 units) ----
        float sf[8][4];
#pragma unroll
        for (int jt = 0; jt < 8; jt++)
#pragma unroll
            for (int i = 0; i < 4; i++) sf[jt][i] = 0.f;

#pragma unroll
        for (int kc = 0; kc < 4; kc++) {
            uint32_t qh[4];
            {
                int r = lane & 7, sel = lane >> 3;
                int row = qw + r + ((sel & 1) << 3);
                int c = kc * 2 + (sel >> 1);
                ldmx4(qh, sb + atile_off(row, c));
            }
#pragma unroll
            for (int g2 = 0; g2 < 4; g2++) {
                uint32_t kh[4], kl[4];
                {
                    int r = lane & 7;
                    int row = g2 * 16 + r + ((lane >> 4) << 3);
                    int c = kc * 2 + ((lane >> 3) & 1);
                    uint32_t off = atile_off(row, c);
                    ldmx4(kh, kst + off);
                    ldmx4(kl, kst + 8192 + off);
                }
#pragma unroll
                for (int jj = 0; jj < 2; jj++) {
                    int jt = g2 * 2 + jj, o2 = jj * 2;
                    mma16816(sf[jt], qh, kh[o2], kh[o2 + 1]);
                    mma16816(sf[jt], qh, kl[o2], kl[o2 + 1]);
                }
            }
        }

        // ---- causal mask (diagonal tiles only) ----
        if (t >= 2 * bx) {
            const int kv0 = t * 64;
            const int r0 = qb + qw + gid, r1 = r0 + 8;
#pragma unroll
            for (int jt = 0; jt < 8; jt++) {
                int col = kv0 + jt * 8 + tig * 2;
                if (col     > r0) sf[jt][0] = -1e30f;
                if (col + 1 > r0) sf[jt][1] = -1e30f;
                if (col     > r1) sf[jt][2] = -1e30f;
                if (col + 1 > r1) sf[jt][3] = -1e30f;
            }
        }

        // ---- online softmax (base-2) ----
        float tm0 = -1e30f, tm1 = -1e30f;
#pragma unroll
        for (int jt = 0; jt < 8; jt++) {
            tm0 = fmaxf(tm0, fmaxf(sf[jt][0], sf[jt][1]));
            tm1 = fmaxf(tm1, fmaxf(sf[jt][2], sf[jt][3]));
        }
        tm0 = fmaxf(tm0, __shfl_xor_sync(0xFFFFFFFFu, tm0, 1));
        tm0 = fmaxf(tm0, __shfl_xor_sync(0xFFFFFFFFu, tm0, 2));
        tm1 = fmaxf(tm1, __shfl_xor_sync(0xFFFFFFFFu, tm1, 1));
        tm1 = fmaxf(tm1, __shfl_xor_sync(0xFFFFFFFFu, tm1, 2));

        float mn0 = fmaxf(fmaxf(m0, tm0), -1e4f);
        float mn1 = fmaxf(fmaxf(m1, tm1), -1e4f);
        float c0 = ex2f(m0 - mn0);
        float c1 = ex2f(m1 - mn1);
        m0 = mn0; m1 = mn1;

        float rs0 = 0.f, rs1 = 0.f;
#pragma unroll
        for (int jt = 0; jt < 8; jt++) {
            sf[jt][0] = ex2f(sf[jt][0] - mn0);
            sf[jt][1] = ex2f(sf[jt][1] - mn0);
            sf[jt][2] = ex2f(sf[jt][2] - mn1);
            sf[jt][3] = ex2f(sf[jt][3] - mn1);
            rs0 += sf[jt][0] + sf[jt][1];
            rs1 += sf[jt][2] + sf[jt][3];
        }
        rs0 += __shfl_xor_sync(0xFFFFFFFFu, rs0, 1);
        rs0 += __shfl_xor_sync(0xFFFFFFFFu, rs0, 2);
        rs1 += __shfl_xor_sync(0xFFFFFFFFu, rs1, 1);
        rs1 += __shfl_xor_sync(0xFFFFFFFFu, rs1, 2);
        l0 = l0 * c0 + rs0;
        l1 = l1 * c1 + rs1;

#pragma unroll
        for (int nt = 0; nt < 8; nt++) {
            o[nt][0] *= c0; o[nt][1] *= c0;
            o[nt][2] *= c1; o[nt][3] *= c1;
        }

        // ---- O += Ph * (Vh + Vl) ----
#pragma unroll
        for (int kc = 0; kc < 4; kc++) {
            uint32_t ph[4];
#pragma unroll
            for (int s = 0; s < 4; s++) {
                int jt = 2 * kc + (s >> 1);
                ph[s] = pack_h2(sf[jt][(s & 1) * 2], sf[jt][(s & 1) * 2 + 1]);
            }
#pragma unroll
            for (int dg = 0; dg < 4; dg++) {
                uint32_t vh[4], vl[4];
                {
                    int r = lane & 7;
                    int row = kc * 16 + r + (((lane >> 3) & 1) << 3);
                    int c = dg * 2 + (lane >> 4);
                    uint32_t off = atile_off(row, c);
                    ldmx4t(vh, kst + 16384 + off);
                    ldmx4t(vl, kst + 24576 + off);
                }
#pragma unroll
                for (int jj = 0; jj < 2; jj++) {
                    int nt = dg * 2 + jj, o2 = jj * 2;
                    mma16816(o[nt], ph, vh[o2], vh[o2 + 1]);
                    mma16816(o[nt], ph, vl[o2], vl[o2 + 1]);
                }
            }
        }
        __syncthreads();
    }

    // ---- epilogue: O / l -> fp16 hi plane ----
    const float inv0 = 1.f / l0;
    const float inv1 = 1.f / l1;
    const size_t tok0 = (size_t)(b * SS + qb + qw + gid) * DM;
#pragma unroll
    for (int nt = 0; nt < 8; nt++) {
        int col = h * 64 + nt * 8 + tig * 2;
        *(uint32_t*)(g_ah + tok0 + col) =
            pack_h2(o[nt][0] * inv0, o[nt][1] * inv0);
        *(uint32_t*)(g_ah + tok0 + 8 * DM + col) =
            pack_h2(o[nt][2] * inv1, o[nt][3] * inv1);
    }
}

// ---------------------------------------------------------------------------
extern "C" void kernel_launch(void* const* d_in, const int* in_sizes, int n_in,
                              void* d_out, int out_size)
{
    const float* x  = (const float*)d_in[0];
    const float* Wq = (const float*)d_in[1];
    const float* Wk = (const float*)d_in[2];
    const float* Wv = (const float*)d_in[3];
    const float* Wo = (const float*)d_in[4];
    const float* bo = (const float*)d_in[5];
    float* out = (float*)d_out;

    cudaFuncSetAttribute(qkv_mma,  cudaFuncAttributeMaxDynamicSharedMemorySize, GEMM_SMEM);
    cudaFuncSetAttribute(o_mma,    cudaFuncAttributeMaxDynamicSharedMemorySize, GEMM_SMEM);
    cudaFuncSetAttribute(attn_mma, cudaFuncAttributeMaxDynamicSharedMemorySize, ATTN_SMEM);

    __half* xh;
    cudaGetSymbolAddress((void**)&xh, g_xh);

    const int nX = MT * DM, nW = DM * DM;
    cvt_x<<<(nX + 255) / 256, 256>>>(x, xh, nX);
    dim3 gw((nW + 255) / 256, 4);
    split_w4<<<gw, 256>>>(Wq, Wk, Wv, Wo);

    dim3 gqkv(DM / 128, MT / 128, 3);
    qkv_mma<<<gqkv, 512, GEMM_SMEM>>>();

    dim3 gattn(SS / 128, BB * NH);
    attn_mma<<<gattn, 256, ATTN_SMEM>>>();

    dim3 go(DM / 128, MT / 128);
    o_mma<<<go, 512, GEMM_SMEM>>>(bo, out);
}

// round 7
// speedup vs baseline: 5.0005x; 1.1873x over previous
#include <cuda_runtime.h>
#include <cuda_fp16.h>
#include <cstdint>

// Problem constants
constexpr int DM = 1024;    // d_model
constexpr int NH = 16;      // heads
constexpr int DH = 64;      // head dim
constexpr int BB = 2;       // batch
constexpr int SS = 2048;    // seq len
constexpr int MT = BB * SS; // 4096 tokens

// softmax scale folded into Q, in log2 domain: 1/sqrt(64) * log2(e)
constexpr float QSCALE = 0.18033688011112042f;

// ---------------------------------------------------------------------------
// Scratch (device globals -- no allocations allowed)
// ---------------------------------------------------------------------------
__device__ __half g_xh[MT * DM];                      // activations: hi only
__device__ __half g_wqhi[DM * DM], g_wqlo[DM * DM];   // weights: hi + lo
__device__ __half g_wkhi[DM * DM], g_wklo[DM * DM];
__device__ __half g_wvhi[DM * DM], g_wvlo[DM * DM];
__device__ __half g_wohi[DM * DM], g_wolo[DM * DM];
__device__ __half g_qh[MT * DM];                      // q: hi only (pre-scaled)
__device__ __half g_khi[MT * DM], g_klo[MT * DM];     // k: hi + lo
__device__ __half g_vhi[MT * DM], g_vlo[MT * DM];     // v: hi + lo
__device__ __half g_ah[MT * DM];                      // attn out: hi only

// ---------------------------------------------------------------------------
// PTX helpers (sm_80-baseline: cp.async, ldmatrix, mma.sync)
// ---------------------------------------------------------------------------
__device__ __forceinline__ uint32_t smem_to_u32(const void* p) {
    uint32_t a;
    asm("{ .reg .u64 t; cvta.to.shared.u64 t, %1; cvt.u32.u64 %0, t; }"
        : "=r"(a) : "l"(p));
    return a;
}
__device__ __forceinline__ void cp_async16(uint32_t dst, const void* src) {
    asm volatile("cp.async.cg.shared.global [%0], [%1], 16;"
                 :: "r"(dst), "l"(src) : "memory");
}
#define CP_COMMIT() asm volatile("cp.async.commit_group;" ::: "memory")
template <int N>
__device__ __forceinline__ void cp_wait() {
    asm volatile("cp.async.wait_group %0;" :: "n"(N) : "memory");
}
__device__ __forceinline__ void ldmx4(uint32_t (&r)[4], uint32_t addr) {
    asm volatile("ldmatrix.sync.aligned.m8n8.x4.shared.b16 {%0,%1,%2,%3}, [%4];"
                 : "=r"(r[0]), "=r"(r[1]), "=r"(r[2]), "=r"(r[3]) : "r"(addr));
}
__device__ __forceinline__ void ldmx4t(uint32_t (&r)[4], uint32_t addr) {
    asm volatile("ldmatrix.sync.aligned.m8n8.x4.trans.shared.b16 {%0,%1,%2,%3}, [%4];"
                 : "=r"(r[0]), "=r"(r[1]), "=r"(r[2]), "=r"(r[3]) : "r"(addr));
}
__device__ __forceinline__ void mma16816(float (&c)[4], const uint32_t (&a)[4],
                                         uint32_t b0, uint32_t b1) {
    asm volatile(
        "mma.sync.aligned.m16n8k16.row.col.f32.f16.f16.f32 "
        "{%0,%1,%2,%3}, {%4,%5,%6,%7}, {%8,%9}, {%0,%1,%2,%3};"
        : "+f"(c[0]), "+f"(c[1]), "+f"(c[2]), "+f"(c[3])
        : "r"(a[0]), "r"(a[1]), "r"(a[2]), "r"(a[3]), "r"(b0), "r"(b1));
}
__device__ __forceinline__ float ex2f(float x) {
    float r;
    asm("ex2.approx.ftz.f32 %0, %1;" : "=f"(r) : "f"(x));
    return r;
}
__device__ __forceinline__ uint32_t pack_h2(float x, float y) {
    __half2 h = __floats2half2_rn(x, y);
    return *reinterpret_cast<uint32_t*>(&h);
}
__device__ __forceinline__ void split_pair_h(float x, float y,
                                             uint32_t& hi, uint32_t& lo) {
    __half2 h = __floats2half2_rn(x, y);
    hi = *reinterpret_cast<uint32_t*>(&h);
    __half2 l = __floats2half2_rn(x - __low2float(h), y - __high2float(h));
    lo = *reinterpret_cast<uint32_t*>(&l);
}

// GEMM tile swizzle (128-row x 32-half, 64B rows)
__device__ __forceinline__ uint32_t tile_off(int row, int kg) {
    return (uint32_t)(row * 64 + (((kg ^ ((row >> 1) & 3)) & 3) << 4));
}
// Attention tile swizzle (rows of 64 half = 128B, 8 chunks of 16B)
__device__ __forceinline__ uint32_t atile_off(int row, int c) {
    return (uint32_t)(row * 128 + (((c ^ (row & 7)) & 7) << 4));
}

// ---------------------------------------------------------------------------
// Input conversion, one launch: grid.y==0..3 -> weights (hi+lo, 1024 blocks);
// grid.y==4..7 -> x quarter-slices (hi only, 1024 blocks each).
// All paths process 4 floats/thread via float4.
// ---------------------------------------------------------------------------
__global__ __launch_bounds__(256) void cvt_all(
    const float* __restrict__ x,
    const float* __restrict__ Wq, const float* __restrict__ Wk,
    const float* __restrict__ Wv, const float* __restrict__ Wo) {
    const int y = blockIdx.y;
    const int i = blockIdx.x * 256 + threadIdx.x;   // 0..262143
    if (y < 4) {
        const float* src = (y == 0) ? Wq : (y == 1) ? Wk : (y == 2) ? Wv : Wo;
        __half* hi = (y == 0) ? g_wqhi : (y == 1) ? g_wkhi : (y == 2) ? g_wvhi : g_wohi;
        __half* lo = (y == 0) ? g_wqlo : (y == 1) ? g_wklo : (y == 2) ? g_wvlo : g_wolo;
        float4 v = ((const float4*)src)[i];
        __half2 h0 = __floats2half2_rn(v.x, v.y);
        __half2 h1 = __floats2half2_rn(v.z, v.w);
        __half2 l0 = __floats2half2_rn(v.x - __low2float(h0), v.y - __high2float(h0));
        __half2 l1 = __floats2half2_rn(v.z - __low2float(h1), v.w - __high2float(h1));
        *(uint2*)(hi + (size_t)i * 4) = make_uint2(*(uint32_t*)&h0, *(uint32_t*)&h1);
        *(uint2*)(lo + (size_t)i * 4) = make_uint2(*(uint32_t*)&l0, *(uint32_t*)&l1);
    } else {
        const size_t base = (size_t)(y - 4) * (MT * DM / 4);
        float4 v = ((const float4*)(x + base))[i];
        uint32_t p0 = pack_h2(v.x, v.y);
        uint32_t p1 = pack_h2(v.z, v.w);
        *(uint2*)(g_xh + base + (size_t)i * 4) = make_uint2(p0, p1);
    }
}

// ---------------------------------------------------------------------------
// fp16x2 tensor-core GEMM: Y = A @ B^T;  A ~ Ah (hi only), B ~ Bh + Bl.
// 128x128 CTA tile, K chunked by 32, 3-stage cp.async.
// 256 threads = 8 warps, warp tile 64x32 (2m x 4n), 2 CTAs/SM.
// Stage: Ah(8KB) | Bh(8KB) | Bl(8KB) = 24KB; 3 stages = 72KB.
// ---------------------------------------------------------------------------
constexpr int GSTAGE = 24576;
constexpr int GEMM_SMEM = 3 * GSTAGE;   // 73728

__device__ __forceinline__ void stage_load(
    uint32_t sbase, int st, const __half* __restrict__ Ah,
    const __half* __restrict__ Bh, const __half* __restrict__ Bl,
    int bm, int bn, int k0, int tid)
{
    const uint32_t base = sbase + st * GSTAGE;
#pragma unroll
    for (int i = 0; i < 6; i++) {
        int idx = tid + 256 * i;          // 0..1535
        int pl  = idx >> 9;               // 0:Ah 1:Bh 2:Bl
        int ci  = idx & 511;
        int row = ci >> 2;
        int kg  = ci & 3;
        const __half* src = (pl == 0) ? Ah : (pl == 1) ? Bh : Bl;
        int rowbase = (pl == 0) ? bm : bn;
        cp_async16(base + pl * 8192 + tile_off(row, kg),
                   src + (size_t)(rowbase + row) * 1024 + k0 + kg * 8);
    }
}

__device__ __forceinline__ void mma_gemm_body(
    const __half* __restrict__ Ah,
    const __half* __restrict__ Bh, const __half* __restrict__ Bl,
    float* __restrict__ Yf32, const float* __restrict__ bias,
    __half* __restrict__ Yhi, __half* __restrict__ Ylo, float oscale)
{
    extern __shared__ char smem[];
    const uint32_t sbase = smem_to_u32(smem);
    const int tid  = threadIdx.x;
    const int wid  = tid >> 5;
    const int lane = tid & 31;
    const int m_base = (wid & 1) * 64;    // 2 m-halves
    const int n_base = (wid >> 1) * 32;   // 4 n-quarters
    const int bm = blockIdx.y * 128;
    const int bn = blockIdx.x * 128;

    float acc[4][4][4];
#pragma unroll
    for (int mt = 0; mt < 4; mt++)
#pragma unroll
        for (int nt = 0; nt < 4; nt++)
#pragma unroll
            for (int i = 0; i < 4; i++) acc[mt][nt][i] = 0.f;

    stage_load(sbase, 0, Ah, Bh, Bl, bm, bn, 0, tid);
    CP_COMMIT();
    stage_load(sbase, 1, Ah, Bh, Bl, bm, bn, 32, tid);
    CP_COMMIT();

    int st_idx = 0;
    for (int kc = 0; kc < 32; kc++) {
        if (kc < 30) {
            stage_load(sbase, (st_idx + 2) % 3, Ah, Bh, Bl, bm, bn,
                       (kc + 2) * 32, tid);
            CP_COMMIT();
            cp_wait<2>();
        } else if (kc == 30) {
            cp_wait<1>();
        } else {
            cp_wait<0>();
        }
        __syncthreads();

        const uint32_t st = sbase + st_idx * GSTAGE;
#pragma unroll
        for (int s = 0; s < 2; s++) {
            uint32_t ah[4][4], bh[2][4], bl[2][4];
            {
                int r   = lane & 7;
                int sel = lane >> 3;
                int kg  = 2 * s + (sel >> 1);
#pragma unroll
                for (int mt = 0; mt < 4; mt++) {
                    int row = m_base + mt * 16 + r + ((sel & 1) << 3);
                    ldmx4(ah[mt], st + tile_off(row, kg));
                }
            }
            {
                int r  = lane & 7;
                int kg = 2 * s + ((lane >> 3) & 1);
#pragma unroll
                for (int ng = 0; ng < 2; ng++) {
                    int row = n_base + ng * 16 + r + ((lane >> 4) << 3);
                    uint32_t off = tile_off(row, kg);
                    ldmx4(bh[ng], st + 8192  + off);
                    ldmx4(bl[ng], st + 16384 + off);
                }
            }
#pragma unroll
            for (int mt = 0; mt < 4; mt++)
#pragma unroll
                for (int nt = 0; nt < 4; nt++) {
                    int g = nt >> 1, o = (nt & 1) * 2;
                    mma16816(acc[mt][nt], ah[mt], bh[g][o], bh[g][o + 1]);
                    mma16816(acc[mt][nt], ah[mt], bl[g][o], bl[g][o + 1]);
                }
        }
        __syncthreads();
        st_idx = (st_idx + 1) % 3;
    }

    const int gid = lane >> 2;
    const int tig = lane & 3;
#pragma unroll
    for (int mt = 0; mt < 4; mt++) {
#pragma unroll
        for (int nt = 0; nt < 4; nt++) {
            int row0 = bm + m_base + mt * 16 + gid;
            int col0 = bn + n_base + nt * 8 + tig * 2;
            if (Yf32) {
                float b0 = bias ? bias[col0]     : 0.f;
                float b1 = bias ? bias[col0 + 1] : 0.f;
                float2 v0 = make_float2(acc[mt][nt][0] + b0, acc[mt][nt][1] + b1);
                float2 v1 = make_float2(acc[mt][nt][2] + b0, acc[mt][nt][3] + b1);
                *(float2*)(Yf32 + (size_t)row0 * 1024 + col0)       = v0;
                *(float2*)(Yf32 + (size_t)(row0 + 8) * 1024 + col0) = v1;
            } else if (Ylo) {
                uint32_t h0, l0, h1, l1;
                split_pair_h(acc[mt][nt][0] * oscale, acc[mt][nt][1] * oscale, h0, l0);
                split_pair_h(acc[mt][nt][2] * oscale, acc[mt][nt][3] * oscale, h1, l1);
                *(uint32_t*)(Yhi + (size_t)row0 * 1024 + col0)       = h0;
                *(uint32_t*)(Ylo + (size_t)row0 * 1024 + col0)       = l0;
                *(uint32_t*)(Yhi + (size_t)(row0 + 8) * 1024 + col0) = h1;
                *(uint32_t*)(Ylo + (size_t)(row0 + 8) * 1024 + col0) = l1;
            } else {
                uint32_t h0 = pack_h2(acc[mt][nt][0] * oscale, acc[mt][nt][1] * oscale);
                uint32_t h1 = pack_h2(acc[mt][nt][2] * oscale, acc[mt][nt][3] * oscale);
                *(uint32_t*)(Yhi + (size_t)row0 * 1024 + col0)       = h0;
                *(uint32_t*)(Yhi + (size_t)(row0 + 8) * 1024 + col0) = h1;
            }
        }
    }
}

__global__ __launch_bounds__(256, 2) void qkv_mma() {
    if (blockIdx.z == 0)
        mma_gemm_body(g_xh, g_wqhi, g_wqlo, nullptr, nullptr, g_qh, nullptr, QSCALE);
    else if (blockIdx.z == 1)
        mma_gemm_body(g_xh, g_wkhi, g_wklo, nullptr, nullptr, g_khi, g_klo, 1.f);
    else
        mma_gemm_body(g_xh, g_wvhi, g_wvlo, nullptr, nullptr, g_vhi, g_vlo, 1.f);
}

__global__ __launch_bounds__(256, 2) void o_mma(const float* __restrict__ bo,
                                                float* __restrict__ out) {
    mma_gemm_body(g_ah, g_wohi, g_wolo, out, bo, nullptr, nullptr, 1.f);
}

// ---------------------------------------------------------------------------
// Tensor-core causal flash attention, fp16x2.
// grid = (S/128, B*H), 256 threads (8 warps, warp = 16 q rows).
// Heavy blocks launched first (bx reversed) to kill the causal tail.
// Q hi resident in smem (16KB); KV stage (Kh,Kl,Vh,Vl = 32KB) x2.
// ---------------------------------------------------------------------------
constexpr int ATTN_SMEM = 16384 + 2 * 32768;  // 81920

__device__ __forceinline__ void attn_load_kv(uint32_t sb, int stage, int kv0,
                                             size_t headoff, int tid) {
#pragma unroll
    for (int i = 0; i < 8; i++) {
        int idx = tid + 256 * i;        // 0..2047
        int pl  = idx >> 9;             // Kh,Kl,Vh,Vl
        int ci  = idx & 511;
        int r   = ci >> 3;
        int c   = ci & 7;
        const __half* base =
            (pl == 0) ? g_khi : (pl == 1) ? g_klo : (pl == 2) ? g_vhi : g_vlo;
        cp_async16(sb + 16384 + stage * 32768 + pl * 8192 + atile_off(r, c),
                   base + headoff + (size_t)(kv0 + r) * DM + c * 8);
    }
    CP_COMMIT();
}

__global__ __launch_bounds__(256) void attn_mma() {
    extern __shared__ char smem[];
    const uint32_t sb = smem_to_u32(smem);
    const int tid  = threadIdx.x;
    const int wid  = tid >> 5;
    const int lane = tid & 31;
    const int gid  = lane >> 2;
    const int tig  = lane & 3;
    const int bx   = gridDim.x - 1 - blockIdx.x;   // heavy blocks first
    const int bh   = blockIdx.y;
    const int b    = bh >> 4;
    const int h    = bh & 15;
    const int qb   = bx * 128;
    const int qw   = wid * 16;
    const size_t headoff = (size_t)(b * SS) * DM + h * 64;

#pragma unroll
    for (int i = 0; i < 4; i++) {
        int idx = tid + 256 * i;
        int r   = idx >> 3;
        int c   = idx & 7;
        cp_async16(sb + atile_off(r, c),
                   g_qh + headoff + (size_t)(qb + r) * DM + c * 8);
    }
    CP_COMMIT();

    float o[8][4];
#pragma unroll
    for (int nt = 0; nt < 8; nt++)
#pragma unroll
        for (int i = 0; i < 4; i++) o[nt][i] = 0.f;
    float m0 = -1e30f, m1 = -1e30f, l0 = 0.f, l1 = 0.f;

    const int ntiles = 2 * bx + 2;
    attn_load_kv(sb, 0, 0, headoff, tid);

    for (int t = 0; t < ntiles; t++) {
        if (t + 1 < ntiles) {
            attn_load_kv(sb, (t + 1) & 1, (t + 1) * 64, headoff, tid);
            cp_wait<1>();
        } else {
            cp_wait<0>();
        }
        __syncthreads();
        const uint32_t kst = sb + 16384 + (t & 1) * 32768;

        float sf[8][4];
#pragma unroll
        for (int jt = 0; jt < 8; jt++)
#pragma unroll
            for (int i = 0; i < 4; i++) sf[jt][i] = 0.f;

#pragma unroll
        for (int kc = 0; kc < 4; kc++) {
            uint32_t qh[4];
            {
                int r = lane & 7, sel = lane >> 3;
                int row = qw + r + ((sel & 1) << 3);
                int c = kc * 2 + (sel >> 1);
                ldmx4(qh, sb + atile_off(row, c));
            }
#pragma unroll
            for (int g2 = 0; g2 < 4; g2++) {
                uint32_t kh[4], kl[4];
                {
                    int r = lane & 7;
                    int row = g2 * 16 + r + ((lane >> 4) << 3);
                    int c = kc * 2 + ((lane >> 3) & 1);
                    uint32_t off = atile_off(row, c);
                    ldmx4(kh, kst + off);
                    ldmx4(kl, kst + 8192 + off);
                }
#pragma unroll
                for (int jj = 0; jj < 2; jj++) {
                    int jt = g2 * 2 + jj, o2 = jj * 2;
                    mma16816(sf[jt], qh, kh[o2], kh[o2 + 1]);
                    mma16816(sf[jt], qh, kl[o2], kl[o2 + 1]);
                }
            }
        }

        if (t >= 2 * bx) {
            const int kv0 = t * 64;
            const int r0 = qb + qw + gid, r1 = r0 + 8;
#pragma unroll
            for (int jt = 0; jt < 8; jt++) {
                int col = kv0 + jt * 8 + tig * 2;
                if (col     > r0) sf[jt][0] = -1e30f;
                if (col + 1 > r0) sf[jt][1] = -1e30f;
                if (col     > r1) sf[jt][2] = -1e30f;
                if (col + 1 > r1) sf[jt][3] = -1e30f;
            }
        }

        float tm0 = -1e30f, tm1 = -1e30f;
#pragma unroll
        for (int jt = 0; jt < 8; jt++) {
            tm0 = fmaxf(tm0, fmaxf(sf[jt][0], sf[jt][1]));
            tm1 = fmaxf(tm1, fmaxf(sf[jt][2], sf[jt][3]));
        }
        tm0 = fmaxf(tm0, __shfl_xor_sync(0xFFFFFFFFu, tm0, 1));
        tm0 = fmaxf(tm0, __shfl_xor_sync(0xFFFFFFFFu, tm0, 2));
        tm1 = fmaxf(tm1, __shfl_xor_sync(0xFFFFFFFFu, tm1, 1));
        tm1 = fmaxf(tm1, __shfl_xor_sync(0xFFFFFFFFu, tm1, 2));

        float mn0 = fmaxf(fmaxf(m0, tm0), -1e4f);
        float mn1 = fmaxf(fmaxf(m1, tm1), -1e4f);
        float c0 = ex2f(m0 - mn0);
        float c1 = ex2f(m1 - mn1);
        m0 = mn0; m1 = mn1;

        float rs0 = 0.f, rs1 = 0.f;
#pragma unroll
        for (int jt = 0; jt < 8; jt++) {
            sf[jt][0] = ex2f(sf[jt][0] - mn0);
            sf[jt][1] = ex2f(sf[jt][1] - mn0);
            sf[jt][2] = ex2f(sf[jt][2] - mn1);
            sf[jt][3] = ex2f(sf[jt][3] - mn1);
            rs0 += sf[jt][0] + sf[jt][1];
            rs1 += sf[jt][2] + sf[jt][3];
        }
        rs0 += __shfl_xor_sync(0xFFFFFFFFu, rs0, 1);
        rs0 += __shfl_xor_sync(0xFFFFFFFFu, rs0, 2);
        rs1 += __shfl_xor_sync(0xFFFFFFFFu, rs1, 1);
        rs1 += __shfl_xor_sync(0xFFFFFFFFu, rs1, 2);
        l0 = l0 * c0 + rs0;
        l1 = l1 * c1 + rs1;

#pragma unroll
        for (int nt = 0; nt < 8; nt++) {
            o[nt][0] *= c0; o[nt][1] *= c0;
            o[nt][2] *= c1; o[nt][3] *= c1;
        }

#pragma unroll
        for (int kc = 0; kc < 4; kc++) {
            uint32_t ph[4];
#pragma unroll
            for (int s = 0; s < 4; s++) {
                int jt = 2 * kc + (s >> 1);
                ph[s] = pack_h2(sf[jt][(s & 1) * 2], sf[jt][(s & 1) * 2 + 1]);
            }
#pragma unroll
            for (int dg = 0; dg < 4; dg++) {
                uint32_t vh[4], vl[4];
                {
                    int r = lane & 7;
                    int row = kc * 16 + r + (((lane >> 3) & 1) << 3);
                    int c = dg * 2 + (lane >> 4);
                    uint32_t off = atile_off(row, c);
                    ldmx4t(vh, kst + 16384 + off);
                    ldmx4t(vl, kst + 24576 + off);
                }
#pragma unroll
                for (int jj = 0; jj < 2; jj++) {
                    int nt = dg * 2 + jj, o2 = jj * 2;
                    mma16816(o[nt], ph, vh[o2], vh[o2 + 1]);
                    mma16816(o[nt], ph, vl[o2], vl[o2 + 1]);
                }
            }
        }
        __syncthreads();
    }

    const float inv0 = 1.f / l0;
    const float inv1 = 1.f / l1;
    const size_t tok0 = (size_t)(b * SS + qb + qw + gid) * DM;
#pragma unroll
    for (int nt = 0; nt < 8; nt++) {
        int col = h * 64 + nt * 8 + tig * 2;
        *(uint32_t*)(g_ah + tok0 + col) =
            pack_h2(o[nt][0] * inv0, o[nt][1] * inv0);
        *(uint32_t*)(g_ah + tok0 + 8 * DM + col) =
            pack_h2(o[nt][2] * inv1, o[nt][3] * inv1);
    }
}

// ---------------------------------------------------------------------------
extern "C" void kernel_launch(void* const* d_in, const int* in_sizes, int n_in,
                              void* d_out, int out_size)
{
    const float* x  = (const float*)d_in[0];
    const float* Wq = (const float*)d_in[1];
    const float* Wk = (const float*)d_in[2];
    const float* Wv = (const float*)d_in[3];
    const float* Wo = (const float*)d_in[4];
    const float* bo = (const float*)d_in[5];
    float* out = (float*)d_out;

    cudaFuncSetAttribute(qkv_mma,  cudaFuncAttributeMaxDynamicSharedMemorySize, GEMM_SMEM);
    cudaFuncSetAttribute(o_mma,    cudaFuncAttributeMaxDynamicSharedMemorySize, GEMM_SMEM);
    cudaFuncSetAttribute(attn_mma, cudaFuncAttributeMaxDynamicSharedMemorySize, ATTN_SMEM);

    // One conversion launch: y 0..3 weights (hi+lo), y 4..7 x quarters (hi)
    cvt_all<<<dim3(1024, 8), 256>>>(x, Wq, Wk, Wv, Wo);

    dim3 gqkv(DM / 128, MT / 128, 3);
    qkv_mma<<<gqkv, 256, GEMM_SMEM>>>();

    dim3 gattn(SS / 128, BB * NH);
    attn_mma<<<gattn, 256, ATTN_SMEM>>>();

    dim3 go(DM / 128, MT / 128);
    o_mma<<<go, 256, GEMM_SMEM>>>(bo, out);
}

// round 9
// speedup vs baseline: 5.0393x; 1.0078x over previous
#include <cuda_runtime.h>
#include <cuda_fp16.h>
#include <cstdint>

// Problem constants
constexpr int DM = 1024;    // d_model
constexpr int NH = 16;      // heads
constexpr int DH = 64;      // head dim
constexpr int BB = 2;       // batch
constexpr int SS = 2048;    // seq len
constexpr int MT = BB * SS; // 4096 tokens

// softmax scale folded into Q, in log2 domain: 1/sqrt(64) * log2(e)
constexpr float QSCALE = 0.18033688011112042f;

// ---------------------------------------------------------------------------
// Scratch (device globals -- no allocations allowed)
// ---------------------------------------------------------------------------
__device__ __half g_xh[MT * DM];                      // activations: hi only
__device__ __half g_wqhi[DM * DM], g_wqlo[DM * DM];   // weights: hi + lo
__device__ __half g_wkhi[DM * DM], g_wklo[DM * DM];
__device__ __half g_wvhi[DM * DM], g_wvlo[DM * DM];
__device__ __half g_wohi[DM * DM], g_wolo[DM * DM];
__device__ __half g_qh[MT * DM];                      // q: hi only (pre-scaled)
__device__ __half g_khi[MT * DM], g_klo[MT * DM];     // k: hi + lo
__device__ __half g_vhi[MT * DM], g_vlo[MT * DM];     // v: hi + lo
__device__ __half g_ah[MT * DM];                      // attn out: hi only

// ---------------------------------------------------------------------------
// PTX helpers (sm_80-baseline: cp.async, ldmatrix, mma.sync)
// ---------------------------------------------------------------------------
__device__ __forceinline__ uint32_t smem_to_u32(const void* p) {
    uint32_t a;
    asm("{ .reg .u64 t; cvta.to.shared.u64 t, %1; cvt.u32.u64 %0, t; }"
        : "=r"(a) : "l"(p));
    return a;
}
__device__ __forceinline__ void cp_async16(uint32_t dst, const void* src) {
    asm volatile("cp.async.cg.shared.global [%0], [%1], 16;"
                 :: "r"(dst), "l"(src) : "memory");
}
#define CP_COMMIT() asm volatile("cp.async.commit_group;" ::: "memory")
template <int N>
__device__ __forceinline__ void cp_wait() {
    asm volatile("cp.async.wait_group %0;" :: "n"(N) : "memory");
}
__device__ __forceinline__ void ldmx4(uint32_t (&r)[4], uint32_t addr) {
    asm volatile("ldmatrix.sync.aligned.m8n8.x4.shared.b16 {%0,%1,%2,%3}, [%4];"
                 : "=r"(r[0]), "=r"(r[1]), "=r"(r[2]), "=r"(r[3]) : "r"(addr));
}
__device__ __forceinline__ void ldmx4t(uint32_t (&r)[4], uint32_t addr) {
    asm volatile("ldmatrix.sync.aligned.m8n8.x4.trans.shared.b16 {%0,%1,%2,%3}, [%4];"
                 : "=r"(r[0]), "=r"(r[1]), "=r"(r[2]), "=r"(r[3]) : "r"(addr));
}
__device__ __forceinline__ void mma16816(float (&c)[4], const uint32_t (&a)[4],
                                         uint32_t b0, uint32_t b1) {
    asm volatile(
        "mma.sync.aligned.m16n8k16.row.col.f32.f16.f16.f32 "
        "{%0,%1,%2,%3}, {%4,%5,%6,%7}, {%8,%9}, {%0,%1,%2,%3};"
        : "+f"(c[0]), "+f"(c[1]), "+f"(c[2]), "+f"(c[3])
        : "r"(a[0]), "r"(a[1]), "r"(a[2]), "r"(a[3]), "r"(b0), "r"(b1));
}
__device__ __forceinline__ float ex2f(float x) {
    float r;
    asm("ex2.approx.ftz.f32 %0, %1;" : "=f"(r) : "f"(x));
    return r;
}
__device__ __forceinline__ uint32_t pack_h2(float x, float y) {
    __half2 h = __floats2half2_rn(x, y);
    return *reinterpret_cast<uint32_t*>(&h);
}
__device__ __forceinline__ void split_pair_h(float x, float y,
                                             uint32_t& hi, uint32_t& lo) {
    __half2 h = __floats2half2_rn(x, y);
    hi = *reinterpret_cast<uint32_t*>(&h);
    __half2 l = __floats2half2_rn(x - __low2float(h), y - __high2float(h));
    lo = *reinterpret_cast<uint32_t*>(&l);
}

// GEMM tile swizzle (128-row x 32-half, 64B rows)
__device__ __forceinline__ uint32_t tile_off(int row, int kg) {
    return (uint32_t)(row * 64 + (((kg ^ ((row >> 1) & 3)) & 3) << 4));
}
// Attention tile swizzle (rows of 64 half = 128B, 8 chunks of 16B)
__device__ __forceinline__ uint32_t atile_off(int row, int c) {
    return (uint32_t)(row * 128 + (((c ^ (row & 7)) & 7) << 4));
}

// ---------------------------------------------------------------------------
// Input conversion, one launch: grid.y==0..3 -> weights (hi+lo);
// grid.y==4..7 -> x quarter-slices (hi only). 4 floats/thread via float4.
// ---------------------------------------------------------------------------
__global__ __launch_bounds__(256) void cvt_all(
    const float* __restrict__ x,
    const float* __restrict__ Wq, const float* __restrict__ Wk,
    const float* __restrict__ Wv, const float* __restrict__ Wo) {
    const int y = blockIdx.y;
    const int i = blockIdx.x * 256 + threadIdx.x;
    if (y < 4) {
        const float* src = (y == 0) ? Wq : (y == 1) ? Wk : (y == 2) ? Wv : Wo;
        __half* hi = (y == 0) ? g_wqhi : (y == 1) ? g_wkhi : (y == 2) ? g_wvhi : g_wohi;
        __half* lo = (y == 0) ? g_wqlo : (y == 1) ? g_wklo : (y == 2) ? g_wvlo : g_wolo;
        float4 v = ((const float4*)src)[i];
        __half2 h0 = __floats2half2_rn(v.x, v.y);
        __half2 h1 = __floats2half2_rn(v.z, v.w);
        __half2 l0 = __floats2half2_rn(v.x - __low2float(h0), v.y - __high2float(h0));
        __half2 l1 = __floats2half2_rn(v.z - __low2float(h1), v.w - __high2float(h1));
        *(uint2*)(hi + (size_t)i * 4) = make_uint2(*(uint32_t*)&h0, *(uint32_t*)&h1);
        *(uint2*)(lo + (size_t)i * 4) = make_uint2(*(uint32_t*)&l0, *(uint32_t*)&l1);
    } else {
        const size_t base = (size_t)(y - 4) * (MT * DM / 4);
        float4 v = ((const float4*)(x + base))[i];
        uint32_t p0 = pack_h2(v.x, v.y);
        uint32_t p1 = pack_h2(v.z, v.w);
        *(uint2*)(g_xh + base + (size_t)i * 4) = make_uint2(p0, p1);
    }
}

// ---------------------------------------------------------------------------
// fp16x2 tensor-core GEMM: Y = A @ B^T;  A ~ Ah (hi only), B ~ Bh + Bl.
// 128x128 CTA tile, K chunked by 32, 4-stage cp.async pipeline,
// ONE __syncthreads per chunk (prefetch issued after the sync into the
// buffer consumed two iterations ago). 256 threads = 8 warps, warp tile
// 64x32 (2m x 4n), 2 CTAs/SM. Stage: Ah|Bh|Bl = 24KB; 4 stages = 96KB.
// ---------------------------------------------------------------------------
constexpr int GSTAGE = 24576;
constexpr int GEMM_SMEM = 4 * GSTAGE;   // 98304

__device__ __forceinline__ void stage_load(
    uint32_t sbase, int st, const __half* __restrict__ Ah,
    const __half* __restrict__ Bh, const __half* __restrict__ Bl,
    int bm, int bn, int k0, int tid)
{
    const uint32_t base = sbase + st * GSTAGE;
#pragma unroll
    for (int i = 0; i < 6; i++) {
        int idx = tid + 256 * i;          // 0..1535
        int pl  = idx >> 9;               // 0:Ah 1:Bh 2:Bl
        int ci  = idx & 511;
        int row = ci >> 2;
        int kg  = ci & 3;
        const __half* src = (pl == 0) ? Ah : (pl == 1) ? Bh : Bl;
        int rowbase = (pl == 0) ? bm : bn;
        cp_async16(base + pl * 8192 + tile_off(row, kg),
                   src + (size_t)(rowbase + row) * 1024 + k0 + kg * 8);
    }
}

__device__ __forceinline__ void mma_gemm_body(
    const __half* __restrict__ Ah,
    const __half* __restrict__ Bh, const __half* __restrict__ Bl,
    float* __restrict__ Yf32, const float* __restrict__ bias,
    __half* __restrict__ Yhi, __half* __restrict__ Ylo, float oscale)
{
    extern __shared__ char smem[];
    const uint32_t sbase = smem_to_u32(smem);
    const int tid  = threadIdx.x;
    const int wid  = tid >> 5;
    const int lane = tid & 31;
    const int m_base = (wid & 1) * 64;    // 2 m-halves
    const int n_base = (wid >> 1) * 32;   // 4 n-quarters
    const int bm = blockIdx.y * 128;
    const int bn = blockIdx.x * 128;

    float acc[4][4][4];
#pragma unroll
    for (int mt = 0; mt < 4; mt++)
#pragma unroll
        for (int nt = 0; nt < 4; nt++)
#pragma unroll
            for (int i = 0; i < 4; i++) acc[mt][nt][i] = 0.f;

    // Preload tiles 0,1,2 into stages 0,1,2
    stage_load(sbase, 0, Ah, Bh, Bl, bm, bn, 0, tid);  CP_COMMIT();
    stage_load(sbase, 1, Ah, Bh, Bl, bm, bn, 32, tid); CP_COMMIT();
    stage_load(sbase, 2, Ah, Bh, Bl, bm, bn, 64, tid); CP_COMMIT();

    for (int kc = 0; kc < 32; kc++) {
        // Guarantee tile kc has landed (tiles kc+1, kc+2 may be pending)
        if (kc < 30)       cp_wait<2>();
        else if (kc == 30) cp_wait<1>();
        else               cp_wait<0>();
        __syncthreads();
        // Prefetch tile kc+3 into the buffer consumed at iteration kc-1
        // (all warps passed the sync => done reading it).
        if (kc < 29) {
            stage_load(sbase, (kc + 3) & 3, Ah, Bh, Bl, bm, bn,
                       (kc + 3) * 32, tid);
            CP_COMMIT();
        }

        const uint32_t st = sbase + (kc & 3) * GSTAGE;
#pragma unroll
        for (int s = 0; s < 2; s++) {
            uint32_t ah[4][4], bh[2][4], bl[2][4];
            {
                int r   = lane & 7;
                int sel = lane >> 3;
                int kg  = 2 * s + (sel >> 1);
#pragma unroll
                for (int mt = 0; mt < 4; mt++) {
                    int row = m_base + mt * 16 + r + ((sel & 1) << 3);
                    ldmx4(ah[mt], st + tile_off(row, kg));
                }
            }
            {
                int r  = lane & 7;
                int kg = 2 * s + ((lane >> 3) & 1);
#pragma unroll
                for (int ng = 0; ng < 2; ng++) {
                    int row = n_base + ng * 16 + r + ((lane >> 4) << 3);
                    uint32_t off = tile_off(row, kg);
                    ldmx4(bh[ng], st + 8192  + off);
                    ldmx4(bl[ng], st + 16384 + off);
                }
            }
#pragma unroll
            for (int mt = 0; mt < 4; mt++)
#pragma unroll
                for (int nt = 0; nt < 4; nt++) {
                    int g = nt >> 1, o = (nt & 1) * 2;
                    mma16816(acc[mt][nt], ah[mt], bh[g][o], bh[g][o + 1]);
                    mma16816(acc[mt][nt], ah[mt], bl[g][o], bl[g][o + 1]);
                }
        }
        // no tail sync: 4 stages + load-after-sync make buffer reuse safe
    }

    const int gid = lane >> 2;
    const int tig = lane & 3;
#pragma unroll
    for (int mt = 0; mt < 4; mt++) {
#pragma unroll
        for (int nt = 0; nt < 4; nt++) {
            int row0 = bm + m_base + mt * 16 + gid;
            int col0 = bn + n_base + nt * 8 + tig * 2;
            if (Yf32) {
                float b0 = bias ? bias[col0]     : 0.f;
                float b1 = bias ? bias[col0 + 1] : 0.f;
                float2 v0 = make_float2(acc[mt][nt][0] + b0, acc[mt][nt][1] + b1);
                float2 v1 = make_float2(acc[mt][nt][2] + b0, acc[mt][nt][3] + b1);
                *(float2*)(Yf32 + (size_t)row0 * 1024 + col0)       = v0;
                *(float2*)(Yf32 + (size_t)(row0 + 8) * 1024 + col0) = v1;
            } else if (Ylo) {
                uint32_t h0, l0, h1, l1;
                split_pair_h(acc[mt][nt][0] * oscale, acc[mt][nt][1] * oscale, h0, l0);
                split_pair_h(acc[mt][nt][2] * oscale, acc[mt][nt][3] * oscale, h1, l1);
                *(uint32_t*)(Yhi + (size_t)row0 * 1024 + col0)       = h0;
                *(uint32_t*)(Ylo + (size_t)row0 * 1024 + col0)       = l0;
                *(uint32_t*)(Yhi + (size_t)(row0 + 8) * 1024 + col0) = h1;
                *(uint32_t*)(Ylo + (size_t)(row0 + 8) * 1024 + col0) = l1;
            } else {
                uint32_t h0 = pack_h2(acc[mt][nt][0] * oscale, acc[mt][nt][1] * oscale);
                uint32_t h1 = pack_h2(acc[mt][nt][2] * oscale, acc[mt][nt][3] * oscale);
                *(uint32_t*)(Yhi + (size_t)row0 * 1024 + col0)       = h0;
                *(uint32_t*)(Yhi + (size_t)(row0 + 8) * 1024 + col0) = h1;
            }
        }
    }
}

__global__ __launch_bounds__(256, 2) void qkv_mma() {
    if (blockIdx.z == 0)
        mma_gemm_body(g_xh, g_wqhi, g_wqlo, nullptr, nullptr, g_qh, nullptr, QSCALE);
    else if (blockIdx.z == 1)
        mma_gemm_body(g_xh, g_wkhi, g_wklo, nullptr, nullptr, g_khi, g_klo, 1.f);
    else
        mma_gemm_body(g_xh, g_wvhi, g_wvlo, nullptr, nullptr, g_vhi, g_vlo, 1.f);
}

__global__ __launch_bounds__(256, 2) void o_mma(const float* __restrict__ bo,
                                                float* __restrict__ out) {
    mma_gemm_body(g_ah, g_wohi, g_wolo, out, bo, nullptr, nullptr, 1.f);
}

// ---------------------------------------------------------------------------
// Tensor-core causal flash attention, fp16x2.
// grid = (S/128, B*H), 256 threads (8 warps, warp = 16 q rows).
// Heavy blocks launched first (bx reversed). Q hi resident (16KB);
// KV stages (Kh,Kl,Vh,Vl = 32KB) x3 with ONE __syncthreads per tile
// (prefetch issued after the sync into the buffer consumed last tile).
// ---------------------------------------------------------------------------
constexpr int ATTN_SMEM = 16384 + 3 * 32768;  // 114688

__device__ __forceinline__ void attn_load_kv(uint32_t sb, int stage, int kv0,
                                             size_t headoff, int tid) {
#pragma unroll
    for (int i = 0; i < 8; i++) {
        int idx = tid + 256 * i;        // 0..2047
        int pl  = idx >> 9;             // Kh,Kl,Vh,Vl
        int ci  = idx & 511;
        int r   = ci >> 3;
        int c   = ci & 7;
        const __half* base =
            (pl == 0) ? g_khi : (pl == 1) ? g_klo : (pl == 2) ? g_vhi : g_vlo;
        cp_async16(sb + 16384 + stage * 32768 + pl * 8192 + atile_off(r, c),
                   base + headoff + (size_t)(kv0 + r) * DM + c * 8);
    }
    CP_COMMIT();
}

__global__ __launch_bounds__(256) void attn_mma() {
    extern __shared__ char smem[];
    const uint32_t sb = smem_to_u32(smem);
    const int tid  = threadIdx.x;
    const int wid  = tid >> 5;
    const int lane = tid & 31;
    const int gid  = lane >> 2;
    const int tig  = lane & 3;
    const int bx   = gridDim.x - 1 - blockIdx.x;   // heavy blocks first
    const int bh   = blockIdx.y;
    const int b    = bh >> 4;
    const int h    = bh & 15;
    const int qb   = bx * 128;
    const int qw   = wid * 16;
    const size_t headoff = (size_t)(b * SS) * DM + h * 64;

    // Q hi preload (group 0)
#pragma unroll
    for (int i = 0; i < 4; i++) {
        int idx = tid + 256 * i;
        int r   = idx >> 3;
        int c   = idx & 7;
        cp_async16(sb + atile_off(r, c),
                   g_qh + headoff + (size_t)(qb + r) * DM + c * 8);
    }
    CP_COMMIT();

    float o[8][4];
#pragma unroll
    for (int nt = 0; nt < 8; nt++)
#pragma unroll
        for (int i = 0; i < 4; i++) o[nt][i] = 0.f;
    float m0 = -1e30f, m1 = -1e30f, l0 = 0.f, l1 = 0.f;

    const int ntiles = 2 * bx + 2;                 // always >= 2
    attn_load_kv(sb, 0, 0, headoff, tid);
    attn_load_kv(sb, 1, 64, headoff, tid);

    for (int t = 0; t < ntiles; t++) {
        // Need Q + kv tile t arrived; at most the next tile may be pending.
        if (t + 1 < ntiles) cp_wait<1>(); else cp_wait<0>();
        __syncthreads();
        // Prefetch tile t+2 into the buffer consumed at tile t-1
        // (all warps passed the sync => done reading it).
        if (t + 2 < ntiles)
            attn_load_kv(sb, (t + 2) % 3, (t + 2) * 64, headoff, tid);

        const uint32_t kst = sb + 16384 + (t % 3) * 32768;

        float sf[8][4];
#pragma unroll
        for (int jt = 0; jt < 8; jt++)
#pragma unroll
            for (int i = 0; i < 4; i++) sf[jt][i] = 0.f;

#pragma unroll
        for (int kc = 0; kc < 4; kc++) {
            uint32_t qh[4];
            {
                int r = lane & 7, sel = lane >> 3;
                int row = qw + r + ((sel & 1) << 3);
                int c = kc * 2 + (sel >> 1);
                ldmx4(qh, sb + atile_off(row, c));
            }
#pragma unroll
            for (int g2 = 0; g2 < 4; g2++) {
                uint32_t kh[4], kl[4];
                {
                    int r = lane & 7;
                    int row = g2 * 16 + r + ((lane >> 4) << 3);
                    int c = kc * 2 + ((lane >> 3) & 1);
                    uint32_t off = atile_off(row, c);
                    ldmx4(kh, kst + off);
                    ldmx4(kl, kst + 8192 + off);
                }
#pragma unroll
                for (int jj = 0; jj < 2; jj++) {
                    int jt = g2 * 2 + jj, o2 = jj * 2;
                    mma16816(sf[jt], qh, kh[o2], kh[o2 + 1]);
                    mma16816(sf[jt], qh, kl[o2], kl[o2 + 1]);
                }
            }
        }

        if (t >= 2 * bx) {
            const int kv0 = t * 64;
            const int r0 = qb + qw + gid, r1 = r0 + 8;
#pragma unroll
            for (int jt = 0; jt < 8; jt++) {
                int col = kv0 + jt * 8 + tig * 2;
                if (col     > r0) sf[jt][0] = -1e30f;
                if (col + 1 > r0) sf[jt][1] = -1e30f;
                if (col     > r1) sf[jt][2] = -1e30f;
                if (col + 1 > r1) sf[jt][3] = -1e30f;
            }
        }

        float tm0 = -1e30f, tm1 = -1e30f;
#pragma unroll
        for (int jt = 0; jt < 8; jt++) {
            tm0 = fmaxf(tm0, fmaxf(sf[jt][0], sf[jt][1]));
            tm1 = fmaxf(tm1, fmaxf(sf[jt][2], sf[jt][3]));
        }
        tm0 = fmaxf(tm0, __shfl_xor_sync(0xFFFFFFFFu, tm0, 1));
        tm0 = fmaxf(tm0, __shfl_xor_sync(0xFFFFFFFFu, tm0, 2));
        tm1 = fmaxf(tm1, __shfl_xor_sync(0xFFFFFFFFu, tm1, 1));
        tm1 = fmaxf(tm1, __shfl_xor_sync(0xFFFFFFFFu, tm1, 2));

        float mn0 = fmaxf(fmaxf(m0, tm0), -1e4f);
        float mn1 = fmaxf(fmaxf(m1, tm1), -1e4f);
        float c0 = ex2f(m0 - mn0);
        float c1 = ex2f(m1 - mn1);
        m0 = mn0; m1 = mn1;

        float rs0 = 0.f, rs1 = 0.f;
#pragma unroll
        for (int jt = 0; jt < 8; jt++) {
            sf[jt][0] = ex2f(sf[jt][0] - mn0);
            sf[jt][1] = ex2f(sf[jt][1] - mn0);
            sf[jt][2] = ex2f(sf[jt][2] - mn1);
            sf[jt][3] = ex2f(sf[jt][3] - mn1);
            rs0 += sf[jt][0] + sf[jt][1];
            rs1 += sf[jt][2] + sf[jt][3];
        }
        rs0 += __shfl_xor_sync(0xFFFFFFFFu, rs0, 1);
        rs0 += __shfl_xor_sync(0xFFFFFFFFu, rs0, 2);
        rs1 += __shfl_xor_sync(0xFFFFFFFFu, rs1, 1);
        rs1 += __shfl_xor_sync(0xFFFFFFFFu, rs1, 2);
        l0 = l0 * c0 + rs0;
        l1 = l1 * c1 + rs1;

#pragma unroll
        for (int nt = 0; nt < 8; nt++) {
            o[nt][0] *= c0; o[nt][1] *= c0;
            o[nt][2] *= c1; o[nt][3] *= c1;
        }

#pragma unroll
        for (int kc = 0; kc < 4; kc++) {
            uint32_t ph[4];
#pragma unroll
            for (int s = 0; s < 4; s++) {
                int jt = 2 * kc + (s >> 1);
                ph[s] = pack_h2(sf[jt][(s & 1) * 2], sf[jt][(s & 1) * 2 + 1]);
            }
#pragma unroll
            for (int dg = 0; dg < 4; dg++) {
                uint32_t vh[4], vl[4];
                {
                    int r = lane & 7;
                    int row = kc * 16 + r + (((lane >> 3) & 1) << 3);
                    int c = dg * 2 + (lane >> 4);
                    uint32_t off = atile_off(row, c);
                    ldmx4t(vh, kst + 16384 + off);
                    ldmx4t(vl, kst + 24576 + off);
                }
#pragma unroll
                for (int jj = 0; jj < 2; jj++) {
                    int nt = dg * 2 + jj, o2 = jj * 2;
                    mma16816(o[nt], ph, vh[o2], vh[o2 + 1]);
                    mma16816(o[nt], ph, vl[o2], vl[o2 + 1]);
                }
            }
        }
        // no tail sync: 3 stages + load-after-sync make buffer reuse safe
    }

    const float inv0 = 1.f / l0;
    const float inv1 = 1.f / l1;
    const size_t tok0 = (size_t)(b * SS + qb + qw + gid) * DM;
#pragma unroll
    for (int nt = 0; nt < 8; nt++) {
        int col = h * 64 + nt * 8 + tig * 2;
        *(uint32_t*)(g_ah + tok0 + col) =
            pack_h2(o[nt][0] * inv0, o[nt][1] * inv0);
        *(uint32_t*)(g_ah + tok0 + 8 * DM + col) =
            pack_h2(o[nt][2] * inv1, o[nt][3] * inv1);
    }
}

// ---------------------------------------------------------------------------
extern "C" void kernel_launch(void* const* d_in, const int* in_sizes, int n_in,
                              void* d_out, int out_size)
{
    const float* x  = (const float*)d_in[0];
    const float* Wq = (const float*)d_in[1];
    const float* Wk = (const float*)d_in[2];
    const float* Wv = (const float*)d_in[3];
    const float* Wo = (const float*)d_in[4];
    const float* bo = (const float*)d_in[5];
    float* out = (float*)d_out;

    cudaFuncSetAttribute(qkv_mma,  cudaFuncAttributeMaxDynamicSharedMemorySize, GEMM_SMEM);
    cudaFuncSetAttribute(o_mma,    cudaFuncAttributeMaxDynamicSharedMemorySize, GEMM_SMEM);
    cudaFuncSetAttribute(attn_mma, cudaFuncAttributeMaxDynamicSharedMemorySize, ATTN_SMEM);

    cvt_all<<<dim3(1024, 8), 256>>>(x, Wq, Wk, Wv, Wo);

    dim3 gqkv(DM / 128, MT / 128, 3);
    qkv_mma<<<gqkv, 256, GEMM_SMEM>>>();

    dim3 gattn(SS / 128, BB * NH);
    attn_mma<<<gattn, 256, ATTN_SMEM>>>();

    dim3 go(DM / 128, MT / 128);
    o_mma<<<go, 256, GEMM_SMEM>>>(bo, out);
}

// round 10
// speedup vs baseline: 8.4759x; 1.6820x over previous
#include <cuda_runtime.h>
#include <cuda_fp16.h>
#include <cstdint>

// Problem constants
constexpr int DM = 1024;    // d_model
constexpr int NH = 16;      // heads
constexpr int DH = 64;      // head dim
constexpr int BB = 2;       // batch
constexpr int SS = 2048;    // seq len
constexpr int MT = BB * SS; // 4096 tokens

// softmax scale folded into Q, in log2 domain: 1/sqrt(64) * log2(e)
constexpr float QSCALE = 0.18033688011112042f;

// ---------------------------------------------------------------------------
// Scratch (device globals -- no allocations allowed). All fp16 hi-only.
// ---------------------------------------------------------------------------
__device__ __half g_xh[MT * DM];
__device__ __half g_wqh[DM * DM], g_wkh[DM * DM], g_wvh[DM * DM], g_woh[DM * DM];
__device__ __half g_qh[MT * DM];   // pre-scaled by QSCALE
__device__ __half g_kh[MT * DM];
__device__ __half g_vh[MT * DM];
__device__ __half g_ah[MT * DM];

// ---------------------------------------------------------------------------
// PTX helpers (sm_80-baseline: cp.async, ldmatrix, mma.sync)
// ---------------------------------------------------------------------------
__device__ __forceinline__ uint32_t smem_to_u32(const void* p) {
    uint32_t a;
    asm("{ .reg .u64 t; cvta.to.shared.u64 t, %1; cvt.u32.u64 %0, t; }"
        : "=r"(a) : "l"(p));
    return a;
}
__device__ __forceinline__ void cp_async16(uint32_t dst, const void* src) {
    asm volatile("cp.async.cg.shared.global [%0], [%1], 16;"
                 :: "r"(dst), "l"(src) : "memory");
}
#define CP_COMMIT() asm volatile("cp.async.commit_group;" ::: "memory")
template <int N>
__device__ __forceinline__ void cp_wait() {
    asm volatile("cp.async.wait_group %0;" :: "n"(N) : "memory");
}
__device__ __forceinline__ void ldmx4(uint32_t (&r)[4], uint32_t addr) {
    asm volatile("ldmatrix.sync.aligned.m8n8.x4.shared.b16 {%0,%1,%2,%3}, [%4];"
                 : "=r"(r[0]), "=r"(r[1]), "=r"(r[2]), "=r"(r[3]) : "r"(addr));
}
__device__ __forceinline__ void ldmx4t(uint32_t (&r)[4], uint32_t addr) {
    asm volatile("ldmatrix.sync.aligned.m8n8.x4.trans.shared.b16 {%0,%1,%2,%3}, [%4];"
                 : "=r"(r[0]), "=r"(r[1]), "=r"(r[2]), "=r"(r[3]) : "r"(addr));
}
__device__ __forceinline__ void mma16816(float (&c)[4], const uint32_t (&a)[4],
                                         uint32_t b0, uint32_t b1) {
    asm volatile(
        "mma.sync.aligned.m16n8k16.row.col.f32.f16.f16.f32 "
        "{%0,%1,%2,%3}, {%4,%5,%6,%7}, {%8,%9}, {%0,%1,%2,%3};"
        : "+f"(c[0]), "+f"(c[1]), "+f"(c[2]), "+f"(c[3])
        : "r"(a[0]), "r"(a[1]), "r"(a[2]), "r"(a[3]), "r"(b0), "r"(b1));
}
__device__ __forceinline__ float ex2f(float x) {
    float r;
    asm("ex2.approx.ftz.f32 %0, %1;" : "=f"(r) : "f"(x));
    return r;
}
__device__ __forceinline__ uint32_t pack_h2(float x, float y) {
    __half2 h = __floats2half2_rn(x, y);
    return *reinterpret_cast<uint32_t*>(&h);
}

// GEMM tile swizzle (128-row x 32-half, 64B rows)
__device__ __forceinline__ uint32_t tile_off(int row, int kg) {
    return (uint32_t)(row * 64 + (((kg ^ ((row >> 1) & 3)) & 3) << 4));
}
// Attention tile swizzle (rows of 64 half = 128B, 8 chunks of 16B)
__device__ __forceinline__ uint32_t atile_off(int row, int c) {
    return (uint32_t)(row * 128 + (((c ^ (row & 7)) & 7) << 4));
}

// ---------------------------------------------------------------------------
// Input conversion (all hi-only now): y 0..3 weights, y 4..7 x quarters.
// 4 floats/thread via float4.
// ---------------------------------------------------------------------------
__global__ __launch_bounds__(256) void cvt_all(
    const float* __restrict__ x,
    const float* __restrict__ Wq, const float* __restrict__ Wk,
    const float* __restrict__ Wv, const float* __restrict__ Wo) {
    const int y = blockIdx.y;
    const int i = blockIdx.x * 256 + threadIdx.x;
    const float* src;
    __half* dst;
    size_t base;
    if (y < 4) {
        src = (y == 0) ? Wq : (y == 1) ? Wk : (y == 2) ? Wv : Wo;
        dst = (y == 0) ? g_wqh : (y == 1) ? g_wkh : (y == 2) ? g_wvh : g_woh;
        base = 0;
    } else {
        src = x;
        dst = g_xh;
        base = (size_t)(y - 4) * (MT * DM / 4);
    }
    float4 v = ((const float4*)(src + base))[i];
    *(uint2*)(dst + base + (size_t)i * 4) =
        make_uint2(pack_h2(v.x, v.y), pack_h2(v.z, v.w));
}

// ---------------------------------------------------------------------------
// Single-pass fp16 tensor-core GEMM: Y = A @ B^T.
// 128x128 CTA tile, K chunked by 32, 4-stage cp.async, one sync per chunk.
// 256 threads = 8 warps, warp tile 64x32 (2m x 4n), 2 CTAs/SM.
// Stage: Ah(8KB) | Bh(8KB) = 16KB; 4 stages = 64KB.
// ---------------------------------------------------------------------------
constexpr int GSTAGE = 16384;
constexpr int GEMM_SMEM = 4 * GSTAGE;   // 65536

__device__ __forceinline__ void stage_load(
    uint32_t sbase, int st, const __half* __restrict__ Ah,
    const __half* __restrict__ Bh, int bm, int bn, int k0, int tid)
{
    const uint32_t base = sbase + st * GSTAGE;
#pragma unroll
    for (int i = 0; i < 4; i++) {
        int idx = tid + 256 * i;          // 0..1023
        int pl  = idx >> 9;               // 0:A 1:B
        int ci  = idx & 511;
        int row = ci >> 2;
        int kg  = ci & 3;
        const __half* src = pl ? Bh : Ah;
        int rowbase = pl ? bn : bm;
        cp_async16(base + pl * 8192 + tile_off(row, kg),
                   src + (size_t)(rowbase + row) * 1024 + k0 + kg * 8);
    }
}

__device__ __forceinline__ void mma_gemm_body(
    const __half* __restrict__ Ah, const __half* __restrict__ Bh,
    float* __restrict__ Yf32, const float* __restrict__ bias,
    __half* __restrict__ Yh, float oscale)
{
    extern __shared__ char smem[];
    const uint32_t sbase = smem_to_u32(smem);
    const int tid  = threadIdx.x;
    const int wid  = tid >> 5;
    const int lane = tid & 31;
    const int m_base = (wid & 1) * 64;    // 2 m-halves
    const int n_base = (wid >> 1) * 32;   // 4 n-quarters
    const int bm = blockIdx.y * 128;
    const int bn = blockIdx.x * 128;

    float acc[4][4][4];
#pragma unroll
    for (int mt = 0; mt < 4; mt++)
#pragma unroll
        for (int nt = 0; nt < 4; nt++)
#pragma unroll
            for (int i = 0; i < 4; i++) acc[mt][nt][i] = 0.f;

    stage_load(sbase, 0, Ah, Bh, bm, bn, 0, tid);  CP_COMMIT();
    stage_load(sbase, 1, Ah, Bh, bm, bn, 32, tid); CP_COMMIT();
    stage_load(sbase, 2, Ah, Bh, bm, bn, 64, tid); CP_COMMIT();

    for (int kc = 0; kc < 32; kc++) {
        if (kc < 30)       cp_wait<2>();
        else if (kc == 30) cp_wait<1>();
        else               cp_wait<0>();
        __syncthreads();
        if (kc < 29) {
            stage_load(sbase, (kc + 3) & 3, Ah, Bh, bm, bn, (kc + 3) * 32, tid);
            CP_COMMIT();
        }

        const uint32_t st = sbase + (kc & 3) * GSTAGE;
#pragma unroll
        for (int s = 0; s < 2; s++) {
            uint32_t ah[4][4], bh[2][4];
            {
                int r   = lane & 7;
                int sel = lane >> 3;
                int kg  = 2 * s + (sel >> 1);
#pragma unroll
                for (int mt = 0; mt < 4; mt++) {
                    int row = m_base + mt * 16 + r + ((sel & 1) << 3);
                    ldmx4(ah[mt], st + tile_off(row, kg));
                }
            }
            {
                int r  = lane & 7;
                int kg = 2 * s + ((lane >> 3) & 1);
#pragma unroll
                for (int ng = 0; ng < 2; ng++) {
                    int row = n_base + ng * 16 + r + ((lane >> 4) << 3);
                    ldmx4(bh[ng], st + 8192 + tile_off(row, kg));
                }
            }
#pragma unroll
            for (int mt = 0; mt < 4; mt++)
#pragma unroll
                for (int nt = 0; nt < 4; nt++) {
                    int g = nt >> 1, o = (nt & 1) * 2;
                    mma16816(acc[mt][nt], ah[mt], bh[g][o], bh[g][o + 1]);
                }
        }
    }

    const int gid = lane >> 2;
    const int tig = lane & 3;
#pragma unroll
    for (int mt = 0; mt < 4; mt++) {
#pragma unroll
        for (int nt = 0; nt < 4; nt++) {
            int row0 = bm + m_base + mt * 16 + gid;
            int col0 = bn + n_base + nt * 8 + tig * 2;
            if (Yf32) {
                float b0 = bias ? bias[col0]     : 0.f;
                float b1 = bias ? bias[col0 + 1] : 0.f;
                float2 v0 = make_float2(acc[mt][nt][0] + b0, acc[mt][nt][1] + b1);
                float2 v1 = make_float2(acc[mt][nt][2] + b0, acc[mt][nt][3] + b1);
                *(float2*)(Yf32 + (size_t)row0 * 1024 + col0)       = v0;
                *(float2*)(Yf32 + (size_t)(row0 + 8) * 1024 + col0) = v1;
            } else {
                uint32_t h0 = pack_h2(acc[mt][nt][0] * oscale, acc[mt][nt][1] * oscale);
                uint32_t h1 = pack_h2(acc[mt][nt][2] * oscale, acc[mt][nt][3] * oscale);
                *(uint32_t*)(Yh + (size_t)row0 * 1024 + col0)       = h0;
                *(uint32_t*)(Yh + (size_t)(row0 + 8) * 1024 + col0) = h1;
            }
        }
    }
}

__global__ __launch_bounds__(256, 2) void qkv_mma() {
    if (blockIdx.z == 0)
        mma_gemm_body(g_xh, g_wqh, nullptr, nullptr, g_qh, QSCALE);
    else if (blockIdx.z == 1)
        mma_gemm_body(g_xh, g_wkh, nullptr, nullptr, g_kh, 1.f);
    else
        mma_gemm_body(g_xh, g_wvh, nullptr, nullptr, g_vh, 1.f);
}

__global__ __launch_bounds__(256, 2) void o_mma(const float* __restrict__ bo,
                                                float* __restrict__ out) {
    mma_gemm_body(g_ah, g_woh, out, bo, nullptr, 1.f);
}

// ---------------------------------------------------------------------------
// Single-pass fp16 causal flash attention.
// grid = (S/128, B*H), 256 threads (8 warps, warp = 16 q rows), 2 CTAs/SM.
// Heavy blocks launched first. Q resident (16KB); KV stage (K|V = 16KB) x3
// with one __syncthreads per tile (load-after-sync rotation). 64KB total.
// ---------------------------------------------------------------------------
constexpr int ASTAGE = 16384;
constexpr int ATTN_SMEM = 16384 + 3 * ASTAGE;  // 65536

__device__ __forceinline__ void attn_load_kv(uint32_t sb, int stage, int kv0,
                                             size_t headoff, int tid) {
#pragma unroll
    for (int i = 0; i < 4; i++) {
        int idx = tid + 256 * i;        // 0..1023
        int pl  = idx >> 9;             // 0:K 1:V
        int ci  = idx & 511;
        int r   = ci >> 3;
        int c   = ci & 7;
        const __half* base = pl ? g_vh : g_kh;
        cp_async16(sb + 16384 + stage * ASTAGE + pl * 8192 + atile_off(r, c),
                   base + headoff + (size_t)(kv0 + r) * DM + c * 8);
    }
    CP_COMMIT();
}

__global__ __launch_bounds__(256, 2) void attn_mma() {
    extern __shared__ char smem[];
    const uint32_t sb = smem_to_u32(smem);
    const int tid  = threadIdx.x;
    const int wid  = tid >> 5;
    const int lane = tid & 31;
    const int gid  = lane >> 2;
    const int tig  = lane & 3;
    const int bx   = gridDim.x - 1 - blockIdx.x;   // heavy blocks first
    const int bh   = blockIdx.y;
    const int b    = bh >> 4;
    const int h    = bh & 15;
    const int qb   = bx * 128;
    const int qw   = wid * 16;
    const size_t headoff = (size_t)(b * SS) * DM + h * 64;

    // Q preload (group 0)
#pragma unroll
    for (int i = 0; i < 4; i++) {
        int idx = tid + 256 * i;
        int r   = idx >> 3;
        int c   = idx & 7;
        cp_async16(sb + atile_off(r, c),
                   g_qh + headoff + (size_t)(qb + r) * DM + c * 8);
    }
    CP_COMMIT();

    float o[8][4];
#pragma unroll
    for (int nt = 0; nt < 8; nt++)
#pragma unroll
        for (int i = 0; i < 4; i++) o[nt][i] = 0.f;
    float m0 = -1e30f, m1 = -1e30f, l0 = 0.f, l1 = 0.f;

    const int ntiles = 2 * bx + 2;
    attn_load_kv(sb, 0, 0, headoff, tid);
    attn_load_kv(sb, 1, 64, headoff, tid);

    for (int t = 0; t < ntiles; t++) {
        if (t + 1 < ntiles) cp_wait<1>(); else cp_wait<0>();
        __syncthreads();
        if (t + 2 < ntiles)
            attn_load_kv(sb, (t + 2) % 3, (t + 2) * 64, headoff, tid);

        const uint32_t kst = sb + 16384 + (t % 3) * ASTAGE;

        float sf[8][4];
#pragma unroll
        for (int jt = 0; jt < 8; jt++)
#pragma unroll
            for (int i = 0; i < 4; i++) sf[jt][i] = 0.f;

#pragma unroll
        for (int kc = 0; kc < 4; kc++) {
            uint32_t qh[4];
            {
                int r = lane & 7, sel = lane >> 3;
                int row = qw + r + ((sel & 1) << 3);
                int c = kc * 2 + (sel >> 1);
                ldmx4(qh, sb + atile_off(row, c));
            }
#pragma unroll
            for (int g2 = 0; g2 < 4; g2++) {
                uint32_t kh[4];
                {
                    int r = lane & 7;
                    int row = g2 * 16 + r + ((lane >> 4) << 3);
                    int c = kc * 2 + ((lane >> 3) & 1);
                    ldmx4(kh, kst + atile_off(row, c));
                }
                mma16816(sf[g2 * 2 + 0], qh, kh[0], kh[1]);
                mma16816(sf[g2 * 2 + 1], qh, kh[2], kh[3]);
            }
        }

        if (t >= 2 * bx) {
            const int kv0 = t * 64;
            const int r0 = qb + qw + gid, r1 = r0 + 8;
#pragma unroll
            for (int jt = 0; jt < 8; jt++) {
                int col = kv0 + jt * 8 + tig * 2;
                if (col     > r0) sf[jt][0] = -1e30f;
                if (col + 1 > r0) sf[jt][1] = -1e30f;
                if (col     > r1) sf[jt][2] = -1e30f;
                if (col + 1 > r1) sf[jt][3] = -1e30f;
            }
        }

        float tm0 = -1e30f, tm1 = -1e30f;
#pragma unroll
        for (int jt = 0; jt < 8; jt++) {
            tm0 = fmaxf(tm0, fmaxf(sf[jt][0], sf[jt][1]));
            tm1 = fmaxf(tm1, fmaxf(sf[jt][2], sf[jt][3]));
        }
        tm0 = fmaxf(tm0, __shfl_xor_sync(0xFFFFFFFFu, tm0, 1));
        tm0 = fmaxf(tm0, __shfl_xor_sync(0xFFFFFFFFu, tm0, 2));
        tm1 = fmaxf(tm1, __shfl_xor_sync(0xFFFFFFFFu, tm1, 1));
        tm1 = fmaxf(tm1, __shfl_xor_sync(0xFFFFFFFFu, tm1, 2));

        float mn0 = fmaxf(fmaxf(m0, tm0), -1e4f);
        float mn1 = fmaxf(fmaxf(m1, tm1), -1e4f);
        float c0 = ex2f(m0 - mn0);
        float c1 = ex2f(m1 - mn1);
        m0 = mn0; m1 = mn1;

        float rs0 = 0.f, rs1 = 0.f;
#pragma unroll
        for (int jt = 0; jt < 8; jt++) {
            sf[jt][0] = ex2f(sf[jt][0] - mn0);
            sf[jt][1] = ex2f(sf[jt][1] - mn0);
            sf[jt][2] = ex2f(sf[jt][2] - mn1);
            sf[jt][3] = ex2f(sf[jt][3] - mn1);
            rs0 += sf[jt][0] + sf[jt][1];
            rs1 += sf[jt][2] + sf[jt][3];
        }
        rs0 += __shfl_xor_sync(0xFFFFFFFFu, rs0, 1);
        rs0 += __shfl_xor_sync(0xFFFFFFFFu, rs0, 2);
        rs1 += __shfl_xor_sync(0xFFFFFFFFu, rs1, 1);
        rs1 += __shfl_xor_sync(0xFFFFFFFFu, rs1, 2);
        l0 = l0 * c0 + rs0;
        l1 = l1 * c1 + rs1;

#pragma unroll
        for (int nt = 0; nt < 8; nt++) {
            o[nt][0] *= c0; o[nt][1] *= c0;
            o[nt][2] *= c1; o[nt][3] *= c1;
        }

#pragma unroll
        for (int kc = 0; kc < 4; kc++) {
            uint32_t ph[4];
#pragma unroll
            for (int s = 0; s < 4; s++) {
                int jt = 2 * kc + (s >> 1);
                ph[s] = pack_h2(sf[jt][(s & 1) * 2], sf[jt][(s & 1) * 2 + 1]);
            }
#pragma unroll
            for (int dg = 0; dg < 4; dg++) {
                uint32_t vh[4];
                {
                    int r = lane & 7;
                    int row = kc * 16 + r + (((lane >> 3) & 1) << 3);
                    int c = dg * 2 + (lane >> 4);
                    ldmx4t(vh, kst + 8192 + atile_off(row, c));
                }
                mma16816(o[dg * 2 + 0], ph, vh[0], vh[1]);
                mma16816(o[dg * 2 + 1], ph, vh[2], vh[3]);
            }
        }
    }

    const float inv0 = 1.f / l0;
    const float inv1 = 1.f / l1;
    const size_t tok0 = (size_t)(b * SS + qb + qw + gid) * DM;
#pragma unroll
    for (int nt = 0; nt < 8; nt++) {
        int col = h * 64 + nt * 8 + tig * 2;
        *(uint32_t*)(g_ah + tok0 + col) =
            pack_h2(o[nt][0] * inv0, o[nt][1] * inv0);
        *(uint32_t*)(g_ah + tok0 + 8 * DM + col) =
            pack_h2(o[nt][2] * inv1, o[nt][3] * inv1);
    }
}

// ---------------------------------------------------------------------------
extern "C" void kernel_launch(void* const* d_in, const int* in_sizes, int n_in,
                              void* d_out, int out_size)
{
    const float* x  = (const float*)d_in[0];
    const float* Wq = (const float*)d_in[1];
    const float* Wk = (const float*)d_in[2];
    const float* Wv = (const float*)d_in[3];
    const float* Wo = (const float*)d_in[4];
    const float* bo = (const float*)d_in[5];
    float* out = (float*)d_out;

    cudaFuncSetAttribute(qkv_mma,  cudaFuncAttributeMaxDynamicSharedMemorySize, GEMM_SMEM);
    cudaFuncSetAttribute(o_mma,    cudaFuncAttributeMaxDynamicSharedMemorySize, GEMM_SMEM);
    cudaFuncSetAttribute(attn_mma, cudaFuncAttributeMaxDynamicSharedMemorySize, ATTN_SMEM);

    cvt_all<<<dim3(1024, 8), 256>>>(x, Wq, Wk, Wv, Wo);

    dim3 gqkv(DM / 128, MT / 128, 3);
    qkv_mma<<<gqkv, 256, GEMM_SMEM>>>();

    dim3 gattn(SS / 128, BB * NH);
    attn_mma<<<gattn, 256, ATTN_SMEM>>>();

    dim3 go(DM / 128, MT / 128);
    o_mma<<<go, 256, GEMM_SMEM>>>(bo, out);
}

// round 11
// speedup vs baseline: 8.6538x; 1.0210x over previous
#include <cuda_runtime.h>
#include <cuda_fp16.h>
#include <cstdint>

// Problem constants
constexpr int DM = 1024;    // d_model
constexpr int NH = 16;      // heads
constexpr int DH = 64;      // head dim
constexpr int BB = 2;       // batch
constexpr int SS = 2048;    // seq len
constexpr int MT = BB * SS; // 4096 tokens

// softmax scale folded into Q, in log2 domain: 1/sqrt(64) * log2(e)
constexpr float QSCALE = 0.18033688011112042f;

// ---------------------------------------------------------------------------
// Scratch (device globals -- no allocations allowed). All fp16 hi-only.
// ---------------------------------------------------------------------------
__device__ __half g_xh[MT * DM];
__device__ __half g_wqh[DM * DM], g_wkh[DM * DM], g_wvh[DM * DM], g_woh[DM * DM];
__device__ __half g_qh[MT * DM];   // pre-scaled by QSCALE
__device__ __half g_kh[MT * DM];
__device__ __half g_vh[MT * DM];
__device__ __half g_ah[MT * DM];

// ---------------------------------------------------------------------------
// PTX helpers (sm_80-baseline: cp.async, ldmatrix, mma.sync)
// ---------------------------------------------------------------------------
__device__ __forceinline__ uint32_t smem_to_u32(const void* p) {
    uint32_t a;
    asm("{ .reg .u64 t; cvta.to.shared.u64 t, %1; cvt.u32.u64 %0, t; }"
        : "=r"(a) : "l"(p));
    return a;
}
__device__ __forceinline__ void cp_async16(uint32_t dst, const void* src) {
    asm volatile("cp.async.cg.shared.global [%0], [%1], 16;"
                 :: "r"(dst), "l"(src) : "memory");
}
#define CP_COMMIT() asm volatile("cp.async.commit_group;" ::: "memory")
template <int N>
__device__ __forceinline__ void cp_wait() {
    asm volatile("cp.async.wait_group %0;" :: "n"(N) : "memory");
}
__device__ __forceinline__ void ldmx4(uint32_t (&r)[4], uint32_t addr) {
    asm volatile("ldmatrix.sync.aligned.m8n8.x4.shared.b16 {%0,%1,%2,%3}, [%4];"
                 : "=r"(r[0]), "=r"(r[1]), "=r"(r[2]), "=r"(r[3]) : "r"(addr));
}
__device__ __forceinline__ void ldmx4t(uint32_t (&r)[4], uint32_t addr) {
    asm volatile("ldmatrix.sync.aligned.m8n8.x4.trans.shared.b16 {%0,%1,%2,%3}, [%4];"
                 : "=r"(r[0]), "=r"(r[1]), "=r"(r[2]), "=r"(r[3]) : "r"(addr));
}
__device__ __forceinline__ void mma16816(float (&c)[4], const uint32_t (&a)[4],
                                         uint32_t b0, uint32_t b1) {
    asm volatile(
        "mma.sync.aligned.m16n8k16.row.col.f32.f16.f16.f32 "
        "{%0,%1,%2,%3}, {%4,%5,%6,%7}, {%8,%9}, {%0,%1,%2,%3};"
        : "+f"(c[0]), "+f"(c[1]), "+f"(c[2]), "+f"(c[3])
        : "r"(a[0]), "r"(a[1]), "r"(a[2]), "r"(a[3]), "r"(b0), "r"(b1));
}
__device__ __forceinline__ float ex2f(float x) {
    float r;
    asm("ex2.approx.ftz.f32 %0, %1;" : "=f"(r) : "f"(x));
    return r;
}
__device__ __forceinline__ uint32_t pack_h2(float x, float y) {
    __half2 h = __floats2half2_rn(x, y);
    return *reinterpret_cast<uint32_t*>(&h);
}

// Tile swizzle for 128B rows (64 halfs), 8 chunks of 16B — conflict-free for
// cp.async writes and every ldmatrix phase (proven in attention since R5).
__device__ __forceinline__ uint32_t atile_off(int row, int c) {
    return (uint32_t)(row * 128 + (((c ^ (row & 7)) & 7) << 4));
}

// ---------------------------------------------------------------------------
// Input conversion (all hi-only): y 0..3 weights, y 4..7 x quarters.
// ---------------------------------------------------------------------------
__global__ __launch_bounds__(256) void cvt_all(
    const float* __restrict__ x,
    const float* __restrict__ Wq, const float* __restrict__ Wk,
    const float* __restrict__ Wv, const float* __restrict__ Wo) {
    const int y = blockIdx.y;
    const int i = blockIdx.x * 256 + threadIdx.x;
    const float* src;
    __half* dst;
    size_t base;
    if (y < 4) {
        src = (y == 0) ? Wq : (y == 1) ? Wk : (y == 2) ? Wv : Wo;
        dst = (y == 0) ? g_wqh : (y == 1) ? g_wkh : (y == 2) ? g_wvh : g_woh;
        base = 0;
    } else {
        src = x;
        dst = g_xh;
        base = (size_t)(y - 4) * (MT * DM / 4);
    }
    float4 v = ((const float4*)(src + base))[i];
    *(uint2*)(dst + base + (size_t)i * 4) =
        make_uint2(pack_h2(v.x, v.y), pack_h2(v.z, v.w));
}

// ---------------------------------------------------------------------------
// Single-pass fp16 tensor-core GEMM: Y = A @ B^T.
// 128x128 CTA tile, K chunked by 64 (BK=64), 3-stage cp.async, ONE
// __syncthreads per chunk (16 total). 256 threads = 8 warps, warp tile
// 64x32 (2m x 4n), 2 CTAs/SM. Stage: A(16KB) | B(16KB) = 32KB; x3 = 96KB.
// ---------------------------------------------------------------------------
constexpr int GSTAGE = 32768;
constexpr int GEMM_SMEM = 3 * GSTAGE;   // 98304

__device__ __forceinline__ void stage_load(
    uint32_t sbase, int st, const __half* __restrict__ Ah,
    const __half* __restrict__ Bh, int bm, int bn, int k0, int tid)
{
    const uint32_t base = sbase + st * GSTAGE;
#pragma unroll
    for (int i = 0; i < 8; i++) {
        int idx = tid + 256 * i;          // 0..2047
        int pl  = idx >> 10;              // 0:A 1:B
        int ci  = idx & 1023;
        int row = ci >> 3;                // 0..127
        int c   = ci & 7;                 // 16B chunk within 128B row
        const __half* src = pl ? Bh : Ah;
        int rowbase = pl ? bn : bm;
        cp_async16(base + pl * 16384 + atile_off(row, c),
                   src + (size_t)(rowbase + row) * 1024 + k0 + c * 8);
    }
}

__device__ __forceinline__ void mma_gemm_body(
    const __half* __restrict__ Ah, const __half* __restrict__ Bh,
    float* __restrict__ Yf32, const float* __restrict__ bias,
    __half* __restrict__ Yh, float oscale)
{
    extern __shared__ char smem[];
    const uint32_t sbase = smem_to_u32(smem);
    const int tid  = threadIdx.x;
    const int wid  = tid >> 5;
    const int lane = tid & 31;
    const int m_base = (wid & 1) * 64;    // 2 m-halves
    const int n_base = (wid >> 1) * 32;   // 4 n-quarters
    const int bm = blockIdx.y * 128;
    const int bn = blockIdx.x * 128;

    float acc[4][4][4];
#pragma unroll
    for (int mt = 0; mt < 4; mt++)
#pragma unroll
        for (int nt = 0; nt < 4; nt++)
#pragma unroll
            for (int i = 0; i < 4; i++) acc[mt][nt][i] = 0.f;

    stage_load(sbase, 0, Ah, Bh, bm, bn, 0, tid);  CP_COMMIT();
    stage_load(sbase, 1, Ah, Bh, bm, bn, 64, tid); CP_COMMIT();

    for (int kc = 0; kc < 16; kc++) {
        if (kc < 15) cp_wait<1>(); else cp_wait<0>();
        __syncthreads();
        // Prefetch chunk kc+2 into buffer consumed at chunk kc-1
        // (all warps passed the sync => done reading it).
        if (kc + 2 < 16) {
            stage_load(sbase, (kc + 2) % 3, Ah, Bh, bm, bn, (kc + 2) * 64, tid);
            CP_COMMIT();
        }

        const uint32_t st = sbase + (kc % 3) * GSTAGE;
#pragma unroll
        for (int s = 0; s < 4; s++) {
            uint32_t ah[4][4], bh[2][4];
            {
                int r   = lane & 7;
                int sel = lane >> 3;
                int c   = 2 * s + (sel >> 1);
#pragma unroll
                for (int mt = 0; mt < 4; mt++) {
                    int row = m_base + mt * 16 + r + ((sel & 1) << 3);
                    ldmx4(ah[mt], st + atile_off(row, c));
                }
            }
            {
                int r = lane & 7;
                int c = 2 * s + ((lane >> 3) & 1);
#pragma unroll
                for (int ng = 0; ng < 2; ng++) {
                    int row = n_base + ng * 16 + r + ((lane >> 4) << 3);
                    ldmx4(bh[ng], st + 16384 + atile_off(row, c));
                }
            }
#pragma unroll
            for (int mt = 0; mt < 4; mt++)
#pragma unroll
                for (int nt = 0; nt < 4; nt++) {
                    int g = nt >> 1, o = (nt & 1) * 2;
                    mma16816(acc[mt][nt], ah[mt], bh[g][o], bh[g][o + 1]);
                }
        }
    }

    const int gid = lane >> 2;
    const int tig = lane & 3;
#pragma unroll
    for (int mt = 0; mt < 4; mt++) {
#pragma unroll
        for (int nt = 0; nt < 4; nt++) {
            int row0 = bm + m_base + mt * 16 + gid;
            int col0 = bn + n_base + nt * 8 + tig * 2;
            if (Yf32) {
                float b0 = bias ? bias[col0]     : 0.f;
                float b1 = bias ? bias[col0 + 1] : 0.f;
                float2 v0 = make_float2(acc[mt][nt][0] + b0, acc[mt][nt][1] + b1);
                float2 v1 = make_float2(acc[mt][nt][2] + b0, acc[mt][nt][3] + b1);
                *(float2*)(Yf32 + (size_t)row0 * 1024 + col0)       = v0;
                *(float2*)(Yf32 + (size_t)(row0 + 8) * 1024 + col0) = v1;
            } else {
                uint32_t h0 = pack_h2(acc[mt][nt][0] * oscale, acc[mt][nt][1] * oscale);
                uint32_t h1 = pack_h2(acc[mt][nt][2] * oscale, acc[mt][nt][3] * oscale);
                *(uint32_t*)(Yh + (size_t)row0 * 1024 + col0)       = h0;
                *(uint32_t*)(Yh + (size_t)(row0 + 8) * 1024 + col0) = h1;
            }
        }
    }
}

__global__ __launch_bounds__(256, 2) void qkv_mma() {
    if (blockIdx.z == 0)
        mma_gemm_body(g_xh, g_wqh, nullptr, nullptr, g_qh, QSCALE);
    else if (blockIdx.z == 1)
        mma_gemm_body(g_xh, g_wkh, nullptr, nullptr, g_kh, 1.f);
    else
        mma_gemm_body(g_xh, g_wvh, nullptr, nullptr, g_vh, 1.f);
}

__global__ __launch_bounds__(256, 2) void o_mma(const float* __restrict__ bo,
                                                float* __restrict__ out) {
    mma_gemm_body(g_ah, g_woh, out, bo, nullptr, 1.f);
}

// ---------------------------------------------------------------------------
// Single-pass fp16 causal flash attention (unchanged from R9).
// grid = (S/128, B*H), 256 threads (8 warps, warp = 16 q rows), 2 CTAs/SM.
// Heavy blocks launched first. Q resident (16KB); KV stage (K|V = 16KB) x3
// with one __syncthreads per tile. 64KB total.
// ---------------------------------------------------------------------------
constexpr int ASTAGE = 16384;
constexpr int ATTN_SMEM = 16384 + 3 * ASTAGE;  // 65536

__device__ __forceinline__ void attn_load_kv(uint32_t sb, int stage, int kv0,
                                             size_t headoff, int tid) {
#pragma unroll
    for (int i = 0; i < 4; i++) {
        int idx = tid + 256 * i;        // 0..1023
        int pl  = idx >> 9;             // 0:K 1:V
        int ci  = idx & 511;
        int r   = ci >> 3;
        int c   = ci & 7;
        const __half* base = pl ? g_vh : g_kh;
        cp_async16(sb + 16384 + stage * ASTAGE + pl * 8192 +
                       (uint32_t)(r * 128 + (((c ^ (r & 7)) & 7) << 4)),
                   base + headoff + (size_t)(kv0 + r) * DM + c * 8);
    }
    CP_COMMIT();
}

__global__ __launch_bounds__(256, 2) void attn_mma() {
    extern __shared__ char smem[];
    const uint32_t sb = smem_to_u32(smem);
    const int tid  = threadIdx.x;
    const int wid  = tid >> 5;
    const int lane = tid & 31;
    const int gid  = lane >> 2;
    const int tig  = lane & 3;
    const int bx   = gridDim.x - 1 - blockIdx.x;   // heavy blocks first
    const int bh   = blockIdx.y;
    const int b    = bh >> 4;
    const int h    = bh & 15;
    const int qb   = bx * 128;
    const int qw   = wid * 16;
    const size_t headoff = (size_t)(b * SS) * DM + h * 64;

#pragma unroll
    for (int i = 0; i < 4; i++) {
        int idx = tid + 256 * i;
        int r   = idx >> 3;
        int c   = idx & 7;
        cp_async16(sb + atile_off(r, c),
                   g_qh + headoff + (size_t)(qb + r) * DM + c * 8);
    }
    CP_COMMIT();

    float o[8][4];
#pragma unroll
    for (int nt = 0; nt < 8; nt++)
#pragma unroll
        for (int i = 0; i < 4; i++) o[nt][i] = 0.f;
    float m0 = -1e30f, m1 = -1e30f, l0 = 0.f, l1 = 0.f;

    const int ntiles = 2 * bx + 2;
    attn_load_kv(sb, 0, 0, headoff, tid);
    attn_load_kv(sb, 1, 64, headoff, tid);

    for (int t = 0; t < ntiles; t++) {
        if (t + 1 < ntiles) cp_wait<1>(); else cp_wait<0>();
        __syncthreads();
        if (t + 2 < ntiles)
            attn_load_kv(sb, (t + 2) % 3, (t + 2) * 64, headoff, tid);

        const uint32_t kst = sb + 16384 + (t % 3) * ASTAGE;

        float sf[8][4];
#pragma unroll
        for (int jt = 0; jt < 8; jt++)
#pragma unroll
            for (int i = 0; i < 4; i++) sf[jt][i] = 0.f;

#pragma unroll
        for (int kc = 0; kc < 4; kc++) {
            uint32_t qh[4];
            {
                int r = lane & 7, sel = lane >> 3;
                int row = qw + r + ((sel & 1) << 3);
                int c = kc * 2 + (sel >> 1);
                ldmx4(qh, sb + atile_off(row, c));
            }
#pragma unroll
            for (int g2 = 0; g2 < 4; g2++) {
                uint32_t kh[4];
                {
                    int r = lane & 7;
                    int row = g2 * 16 + r + ((lane >> 4) << 3);
                    int c = kc * 2 + ((lane >> 3) & 1);
                    ldmx4(kh, kst + atile_off(row, c));
                }
                mma16816(sf[g2 * 2 + 0], qh, kh[0], kh[1]);
                mma16816(sf[g2 * 2 + 1], qh, kh[2], kh[3]);
            }
        }

        if (t >= 2 * bx) {
            const int kv0 = t * 64;
            const int r0 = qb + qw + gid, r1 = r0 + 8;
#pragma unroll
            for (int jt = 0; jt < 8; jt++) {
                int col = kv0 + jt * 8 + tig * 2;
                if (col     > r0) sf[jt][0] = -1e30f;
                if (col + 1 > r0) sf[jt][1] = -1e30f;
                if (col     > r1) sf[jt][2] = -1e30f;
                if (col + 1 > r1) sf[jt][3] = -1e30f;
            }
        }

        float tm0 = -1e30f, tm1 = -1e30f;
#pragma unroll
        for (int jt = 0; jt < 8; jt++) {
            tm0 = fmaxf(tm0, fmaxf(sf[jt][0], sf[jt][1]));
            tm1 = fmaxf(tm1, fmaxf(sf[jt][2], sf[jt][3]));
        }
        tm0 = fmaxf(tm0, __shfl_xor_sync(0xFFFFFFFFu, tm0, 1));
        tm0 = fmaxf(tm0, __shfl_xor_sync(0xFFFFFFFFu, tm0, 2));
        tm1 = fmaxf(tm1, __shfl_xor_sync(0xFFFFFFFFu, tm1, 1));
        tm1 = fmaxf(tm1, __shfl_xor_sync(0xFFFFFFFFu, tm1, 2));

        float mn0 = fmaxf(fmaxf(m0, tm0), -1e4f);
        float mn1 = fmaxf(fmaxf(m1, tm1), -1e4f);
        float c0 = ex2f(m0 - mn0);
        float c1 = ex2f(m1 - mn1);
        m0 = mn0; m1 = mn1;

        float rs0 = 0.f, rs1 = 0.f;
#pragma unroll
        for (int jt = 0; jt < 8; jt++) {
            sf[jt][0] = ex2f(sf[jt][0] - mn0);
            sf[jt][1] = ex2f(sf[jt][1] - mn0);
            sf[jt][2] = ex2f(sf[jt][2] - mn1);
            sf[jt][3] = ex2f(sf[jt][3] - mn1);
            rs0 += sf[jt][0] + sf[jt][1];
            rs1 += sf[jt][2] + sf[jt][3];
        }
        rs0 += __shfl_xor_sync(0xFFFFFFFFu, rs0, 1);
        rs0 += __shfl_xor_sync(0xFFFFFFFFu, rs0, 2);
        rs1 += __shfl_xor_sync(0xFFFFFFFFu, rs1, 1);
        rs1 += __shfl_xor_sync(0xFFFFFFFFu, rs1, 2);
        l0 = l0 * c0 + rs0;
        l1 = l1 * c1 + rs1;

#pragma unroll
        for (int nt = 0; nt < 8; nt++) {
            o[nt][0] *= c0; o[nt][1] *= c0;
            o[nt][2] *= c1; o[nt][3] *= c1;
        }

#pragma unroll
        for (int kc = 0; kc < 4; kc++) {
            uint32_t ph[4];
#pragma unroll
            for (int s = 0; s < 4; s++) {
                int jt = 2 * kc + (s >> 1);
                ph[s] = pack_h2(sf[jt][(s & 1) * 2], sf[jt][(s & 1) * 2 + 1]);
            }
#pragma unroll
            for (int dg = 0; dg < 4; dg++) {
                uint32_t vh[4];
                {
                    int r = lane & 7;
                    int row = kc * 16 + r + (((lane >> 3) & 1) << 3);
                    int c = dg * 2 + (lane >> 4);
                    ldmx4t(vh, kst + 8192 + atile_off(row, c));
                }
                mma16816(o[dg * 2 + 0], ph, vh[0], vh[1]);
                mma16816(o[dg * 2 + 1], ph, vh[2], vh[3]);
            }
        }
    }

    const float inv0 = 1.f / l0;
    const float inv1 = 1.f / l1;
    const size_t tok0 = (size_t)(b * SS + qb + qw + gid) * DM;
#pragma unroll
    for (int nt = 0; nt < 8; nt++) {
        int col = h * 64 + nt * 8 + tig * 2;
        *(uint32_t*)(g_ah + tok0 + col) =
            pack_h2(o[nt][0] * inv0, o[nt][1] * inv0);
        *(uint32_t*)(g_ah + tok0 + 8 * DM + col) =
            pack_h2(o[nt][2] * inv1, o[nt][3] * inv1);
    }
}

// ---------------------------------------------------------------------------
extern "C" void kernel_launch(void* const* d_in, const int* in_sizes, int n_in,
                              void* d_out, int out_size)
{
    const float* x  = (const float*)d_in[0];
    const float* Wq = (const float*)d_in[1];
    const float* Wk = (const float*)d_in[2];
    const float* Wv = (const float*)d_in[3];
    const float* Wo = (const float*)d_in[4];
    const float* bo = (const float*)d_in[5];
    float* out = (float*)d_out;

    cudaFuncSetAttribute(qkv_mma,  cudaFuncAttributeMaxDynamicSharedMemorySize, GEMM_SMEM);
    cudaFuncSetAttribute(o_mma,    cudaFuncAttributeMaxDynamicSharedMemorySize, GEMM_SMEM);
    cudaFuncSetAttribute(attn_mma, cudaFuncAttributeMaxDynamicSharedMemorySize, ATTN_SMEM);

    cvt_all<<<dim3(1024, 8), 256>>>(x, Wq, Wk, Wv, Wo);

    dim3 gqkv(DM / 128, MT / 128, 3);
    qkv_mma<<<gqkv, 256, GEMM_SMEM>>>();

    dim3 gattn(SS / 128, BB * NH);
    attn_mma<<<gattn, 256, ATTN_SMEM>>>();

    dim3 go(DM / 128, MT / 128);
    o_mma<<<go, 256, GEMM_SMEM>>>(bo, out);
}

// round 12
// speedup vs baseline: 8.8071x; 1.0177x over previous
#include <cuda_runtime.h>
#include <cuda_fp16.h>
#include <cstdint>

// Problem constants
constexpr int DM = 1024;    // d_model
constexpr int NH = 16;      // heads
constexpr int DH = 64;      // head dim
constexpr int BB = 2;       // batch
constexpr int SS = 2048;    // seq len
constexpr int MT = BB * SS; // 4096 tokens

// softmax scale folded into Q, in log2 domain: 1/sqrt(64) * log2(e)
constexpr float QSCALE = 0.18033688011112042f;

// ---------------------------------------------------------------------------
// Scratch (device globals -- no allocations allowed). All fp16 hi-only.
// ---------------------------------------------------------------------------
__device__ __half g_xh[MT * DM];
__device__ __half g_wqh[DM * DM], g_wkh[DM * DM], g_wvh[DM * DM], g_woh[DM * DM];
__device__ __half g_qh[MT * DM];   // pre-scaled by QSCALE
__device__ __half g_kh[MT * DM];
__device__ __half g_vh[MT * DM];
__device__ __half g_ah[MT * DM];

// ---------------------------------------------------------------------------
// PTX helpers (sm_80-baseline: cp.async, ldmatrix, mma.sync)
// ---------------------------------------------------------------------------
__device__ __forceinline__ uint32_t smem_to_u32(const void* p) {
    uint32_t a;
    asm("{ .reg .u64 t; cvta.to.shared.u64 t, %1; cvt.u32.u64 %0, t; }"
        : "=r"(a) : "l"(p));
    return a;
}
__device__ __forceinline__ void cp_async16(uint32_t dst, const void* src) {
    asm volatile("cp.async.cg.shared.global [%0], [%1], 16;"
                 :: "r"(dst), "l"(src) : "memory");
}
#define CP_COMMIT() asm volatile("cp.async.commit_group;" ::: "memory")
template <int N>
__device__ __forceinline__ void cp_wait() {
    asm volatile("cp.async.wait_group %0;" :: "n"(N) : "memory");
}
__device__ __forceinline__ void ldmx4(uint32_t (&r)[4], uint32_t addr) {
    asm volatile("ldmatrix.sync.aligned.m8n8.x4.shared.b16 {%0,%1,%2,%3}, [%4];"
                 : "=r"(r[0]), "=r"(r[1]), "=r"(r[2]), "=r"(r[3]) : "r"(addr));
}
__device__ __forceinline__ void ldmx4t(uint32_t (&r)[4], uint32_t addr) {
    asm volatile("ldmatrix.sync.aligned.m8n8.x4.trans.shared.b16 {%0,%1,%2,%3}, [%4];"
                 : "=r"(r[0]), "=r"(r[1]), "=r"(r[2]), "=r"(r[3]) : "r"(addr));
}
__device__ __forceinline__ void mma16816(float (&c)[4], const uint32_t (&a)[4],
                                         uint32_t b0, uint32_t b1) {
    asm volatile(
        "mma.sync.aligned.m16n8k16.row.col.f32.f16.f16.f32 "
        "{%0,%1,%2,%3}, {%4,%5,%6,%7}, {%8,%9}, {%0,%1,%2,%3};"
        : "+f"(c[0]), "+f"(c[1]), "+f"(c[2]), "+f"(c[3])
        : "r"(a[0]), "r"(a[1]), "r"(a[2]), "r"(a[3]), "r"(b0), "r"(b1));
}
__device__ __forceinline__ float ex2f(float x) {
    float r;
    asm("ex2.approx.ftz.f32 %0, %1;" : "=f"(r) : "f"(x));
    return r;
}
__device__ __forceinline__ uint32_t h2ex2(uint32_t x) {
    uint32_t r;
    asm("ex2.approx.f16x2 %0, %1;" : "=r"(r) : "r"(x));
    return r;
}
__device__ __forceinline__ uint32_t hmax2u(uint32_t a, uint32_t b) {
    __half2 r = __hmax2(*reinterpret_cast<__half2*>(&a),
                        *reinterpret_cast<__half2*>(&b));
    return *reinterpret_cast<uint32_t*>(&r);
}
__device__ __forceinline__ uint32_t pack_h2(float x, float y) {
    __half2 h = __floats2half2_rn(x, y);
    return *reinterpret_cast<uint32_t*>(&h);
}
__device__ __forceinline__ float2 h2f2(uint32_t p) {
    return __half22float2(*reinterpret_cast<__half2*>(&p));
}

// Tile swizzle for 128B rows (64 halfs), 8 chunks of 16B — conflict-free for
// cp.async writes and every ldmatrix phase.
__device__ __forceinline__ uint32_t atile_off(int row, int c) {
    return (uint32_t)(row * 128 + (((c ^ (row & 7)) & 7) << 4));
}

// ---------------------------------------------------------------------------
// Input conversion (all hi-only): y 0..3 weights, y 4..7 x quarters.
// ---------------------------------------------------------------------------
__global__ __launch_bounds__(256) void cvt_all(
    const float* __restrict__ x,
    const float* __restrict__ Wq, const float* __restrict__ Wk,
    const float* __restrict__ Wv, const float* __restrict__ Wo) {
    const int y = blockIdx.y;
    const int i = blockIdx.x * 256 + threadIdx.x;
    const float* src;
    __half* dst;
    size_t base;
    if (y < 4) {
        src = (y == 0) ? Wq : (y == 1) ? Wk : (y == 2) ? Wv : Wo;
        dst = (y == 0) ? g_wqh : (y == 1) ? g_wkh : (y == 2) ? g_wvh : g_woh;
        base = 0;
    } else {
        src = x;
        dst = g_xh;
        base = (size_t)(y - 4) * (MT * DM / 4);
    }
    float4 v = ((const float4*)(src + base))[i];
    *(uint2*)(dst + base + (size_t)i * 4) =
        make_uint2(pack_h2(v.x, v.y), pack_h2(v.z, v.w));
}

// ---------------------------------------------------------------------------
// Single-pass fp16 tensor-core GEMM: Y = A @ B^T.
// 128x128 CTA tile, BK=64, 3-stage cp.async, one sync per chunk.
// 256 threads = 8 warps, warp tile 64x32, 2 CTAs/SM.
// NEW: B-fragment double buffering across s-steps (dependency-stall probe).
// ---------------------------------------------------------------------------
constexpr int GSTAGE = 32768;
constexpr int GEMM_SMEM = 3 * GSTAGE;   // 98304

__device__ __forceinline__ void stage_load(
    uint32_t sbase, int st, const __half* __restrict__ Ah,
    const __half* __restrict__ Bh, int bm, int bn, int k0, int tid)
{
    const uint32_t base = sbase + st * GSTAGE;
#pragma unroll
    for (int i = 0; i < 8; i++) {
        int idx = tid + 256 * i;          // 0..2047
        int pl  = idx >> 10;              // 0:A 1:B
        int ci  = idx & 1023;
        int row = ci >> 3;                // 0..127
        int c   = ci & 7;                 // 16B chunk within 128B row
        const __half* src = pl ? Bh : Ah;
        int rowbase = pl ? bn : bm;
        cp_async16(base + pl * 16384 + atile_off(row, c),
                   src + (size_t)(rowbase + row) * 1024 + k0 + c * 8);
    }
}

__device__ __forceinline__ void mma_gemm_body(
    const __half* __restrict__ Ah, const __half* __restrict__ Bh,
    float* __restrict__ Yf32, const float* __restrict__ bias,
    __half* __restrict__ Yh, float oscale)
{
    extern __shared__ char smem[];
    const uint32_t sbase = smem_to_u32(smem);
    const int tid  = threadIdx.x;
    const int wid  = tid >> 5;
    const int lane = tid & 31;
    const int m_base = (wid & 1) * 64;    // 2 m-halves
    const int n_base = (wid >> 1) * 32;   // 4 n-quarters
    const int bm = blockIdx.y * 128;
    const int bn = blockIdx.x * 128;

    float acc[4][4][4];
#pragma unroll
    for (int mt = 0; mt < 4; mt++)
#pragma unroll
        for (int nt = 0; nt < 4; nt++)
#pragma unroll
            for (int i = 0; i < 4; i++) acc[mt][nt][i] = 0.f;

    stage_load(sbase, 0, Ah, Bh, bm, bn, 0, tid);  CP_COMMIT();
    stage_load(sbase, 1, Ah, Bh, bm, bn, 64, tid); CP_COMMIT();

    // B-fragment addressing constants
    const int br  = lane & 7;
    const int bc0 = (lane >> 3) & 1;
    const int bro = (lane >> 4) << 3;

    for (int kc = 0; kc < 16; kc++) {
        if (kc < 15) cp_wait<1>(); else cp_wait<0>();
        __syncthreads();
        if (kc + 2 < 16) {
            stage_load(sbase, (kc + 2) % 3, Ah, Bh, bm, bn, (kc + 2) * 64, tid);
            CP_COMMIT();
        }

        const uint32_t st = sbase + (kc % 3) * GSTAGE;

        // Preload B fragments for s=0
        uint32_t bh[2][2][4];
#pragma unroll
        for (int ng = 0; ng < 2; ng++) {
            int row = n_base + ng * 16 + br + bro;
            ldmx4(bh[0][ng], st + 16384 + atile_off(row, bc0));
        }

#pragma unroll
        for (int s = 0; s < 4; s++) {
            uint32_t ah[4][4];
            {
                int r   = lane & 7;
                int sel = lane >> 3;
                int c   = 2 * s + (sel >> 1);
#pragma unroll
                for (int mt = 0; mt < 4; mt++) {
                    int row = m_base + mt * 16 + r + ((sel & 1) << 3);
                    ldmx4(ah[mt], st + atile_off(row, c));
                }
            }
            // Prefetch B fragments for s+1 before issuing this step's MMAs
            if (s < 3) {
                int c = 2 * (s + 1) + bc0;
#pragma unroll
                for (int ng = 0; ng < 2; ng++) {
                    int row = n_base + ng * 16 + br + bro;
                    ldmx4(bh[(s + 1) & 1][ng], st + 16384 + atile_off(row, c));
                }
            }
            const int cb = s & 1;
#pragma unroll
            for (int mt = 0; mt < 4; mt++)
#pragma unroll
                for (int nt = 0; nt < 4; nt++) {
                    int g = nt >> 1, o = (nt & 1) * 2;
                    mma16816(acc[mt][nt], ah[mt], bh[cb][g][o], bh[cb][g][o + 1]);
                }
        }
    }

    const int gid = lane >> 2;
    const int tig = lane & 3;
#pragma unroll
    for (int mt = 0; mt < 4; mt++) {
#pragma unroll
        for (int nt = 0; nt < 4; nt++) {
            int row0 = bm + m_base + mt * 16 + gid;
            int col0 = bn + n_base + nt * 8 + tig * 2;
            if (Yf32) {
                float b0 = bias ? bias[col0]     : 0.f;
                float b1 = bias ? bias[col0 + 1] : 0.f;
                float2 v0 = make_float2(acc[mt][nt][0] + b0, acc[mt][nt][1] + b1);
                float2 v1 = make_float2(acc[mt][nt][2] + b0, acc[mt][nt][3] + b1);
                *(float2*)(Yf32 + (size_t)row0 * 1024 + col0)       = v0;
                *(float2*)(Yf32 + (size_t)(row0 + 8) * 1024 + col0) = v1;
            } else {
                uint32_t h0 = pack_h2(acc[mt][nt][0] * oscale, acc[mt][nt][1] * oscale);
                uint32_t h1 = pack_h2(acc[mt][nt][2] * oscale, acc[mt][nt][3] * oscale);
                *(uint32_t*)(Yh + (size_t)row0 * 1024 + col0)       = h0;
                *(uint32_t*)(Yh + (size_t)(row0 + 8) * 1024 + col0) = h1;
            }
        }
    }
}

__global__ __launch_bounds__(256, 2) void qkv_mma() {
    if (blockIdx.z == 0)
        mma_gemm_body(g_xh, g_wqh, nullptr, nullptr, g_qh, QSCALE);
    else if (blockIdx.z == 1)
        mma_gemm_body(g_xh, g_wkh, nullptr, nullptr, g_kh, 1.f);
    else
        mma_gemm_body(g_xh, g_wvh, nullptr, nullptr, g_vh, 1.f);
}

__global__ __launch_bounds__(256, 2) void o_mma(const float* __restrict__ bo,
                                                float* __restrict__ out) {
    mma_gemm_body(g_ah, g_woh, out, bo, nullptr, 1.f);
}

// ---------------------------------------------------------------------------
// Single-pass fp16 causal flash attention, f16x2-exp softmax.
// grid = (S/128, B*H), 256 threads (8 warps, warp = 16 q rows), 2 CTAs/SM.
// Heavy blocks launched first. Q resident (16KB); KV stage (K|V = 16KB) x3.
// ---------------------------------------------------------------------------
constexpr int ASTAGE = 16384;
constexpr int ATTN_SMEM = 16384 + 3 * ASTAGE;  // 65536

__device__ __forceinline__ void attn_load_kv(uint32_t sb, int stage, int kv0,
                                             size_t headoff, int tid) {
#pragma unroll
    for (int i = 0; i < 4; i++) {
        int idx = tid + 256 * i;        // 0..1023
        int pl  = idx >> 9;             // 0:K 1:V
        int ci  = idx & 511;
        int r   = ci >> 3;
        int c   = ci & 7;
        const __half* base = pl ? g_vh : g_kh;
        cp_async16(sb + 16384 + stage * ASTAGE + pl * 8192 + atile_off(r, c),
                   base + headoff + (size_t)(kv0 + r) * DM + c * 8);
    }
    CP_COMMIT();
}

__global__ __launch_bounds__(256, 2) void attn_mma() {
    extern __shared__ char smem[];
    const uint32_t sb = smem_to_u32(smem);
    const int tid  = threadIdx.x;
    const int wid  = tid >> 5;
    const int lane = tid & 31;
    const int gid  = lane >> 2;
    const int tig  = lane & 3;
    const int bx   = gridDim.x - 1 - blockIdx.x;   // heavy blocks first
    const int bh   = blockIdx.y;
    const int b    = bh >> 4;
    const int h    = bh & 15;
    const int qb   = bx * 128;
    const int qw   = wid * 16;
    const size_t headoff = (size_t)(b * SS) * DM + h * 64;

#pragma unroll
    for (int i = 0; i < 4; i++) {
        int idx = tid + 256 * i;
        int r   = idx >> 3;
        int c   = idx & 7;
        cp_async16(sb + atile_off(r, c),
                   g_qh + headoff + (size_t)(qb + r) * DM + c * 8);
    }
    CP_COMMIT();

    float o[8][4];
#pragma unroll
    for (int nt = 0; nt < 8; nt++)
#pragma unroll
        for (int i = 0; i < 4; i++) o[nt][i] = 0.f;
    float m0 = -1e30f, m1 = -1e30f, l0 = 0.f, l1 = 0.f;

    const int ntiles = 2 * bx + 2;
    attn_load_kv(sb, 0, 0, headoff, tid);
    attn_load_kv(sb, 1, 64, headoff, tid);

    for (int t = 0; t < ntiles; t++) {
        if (t + 1 < ntiles) cp_wait<1>(); else cp_wait<0>();
        __syncthreads();
        if (t + 2 < ntiles)
            attn_load_kv(sb, (t + 2) % 3, (t + 2) * 64, headoff, tid);

        const uint32_t kst = sb + 16384 + (t % 3) * ASTAGE;

        float sf[8][4];
#pragma unroll
        for (int jt = 0; jt < 8; jt++)
#pragma unroll
            for (int i = 0; i < 4; i++) sf[jt][i] = 0.f;

        // ---- S = Q * K^T (log2 units) ----
#pragma unroll
        for (int kc = 0; kc < 4; kc++) {
            uint32_t qh[4];
            {
                int r = lane & 7, sel = lane >> 3;
                int row = qw + r + ((sel & 1) << 3);
                int c = kc * 2 + (sel >> 1);
                ldmx4(qh, sb + atile_off(row, c));
            }
#pragma unroll
            for (int g2 = 0; g2 < 4; g2++) {
                uint32_t kh[4];
                {
                    int r = lane & 7;
                    int row = g2 * 16 + r + ((lane >> 4) << 3);
                    int c = kc * 2 + ((lane >> 3) & 1);
                    ldmx4(kh, kst + atile_off(row, c));
                }
                mma16816(sf[g2 * 2 + 0], qh, kh[0], kh[1]);
                mma16816(sf[g2 * 2 + 1], qh, kh[2], kh[3]);
            }
        }

        // ---- causal mask (diagonal tiles only) ----
        if (t >= 2 * bx) {
            const int kv0 = t * 64;
            const int r0 = qb + qw + gid, r1 = r0 + 8;
#pragma unroll
            for (int jt = 0; jt < 8; jt++) {
                int col = kv0 + jt * 8 + tig * 2;
                if (col     > r0) sf[jt][0] = -1e30f;
                if (col + 1 > r0) sf[jt][1] = -1e30f;
                if (col     > r1) sf[jt][2] = -1e30f;
                if (col + 1 > r1) sf[jt][3] = -1e30f;
            }
        }

        // ---- online softmax (base-2), f16x2 exp ----
        float tm0 = -1e30f, tm1 = -1e30f;
#pragma unroll
        for (int jt = 0; jt < 8; jt++) {
            tm0 = fmaxf(tm0, fmaxf(sf[jt][0], sf[jt][1]));
            tm1 = fmaxf(tm1, fmaxf(sf[jt][2], sf[jt][3]));
        }
        // packed half2 max reduction across the 4-thread row group
        uint32_t tm2 = pack_h2(tm0, tm1);
        tm2 = hmax2u(tm2, __shfl_xor_sync(0xFFFFFFFFu, tm2, 1));
        tm2 = hmax2u(tm2, __shfl_xor_sync(0xFFFFFFFFu, tm2, 2));
        float2 tmf = h2f2(tm2);

        float mn0 = fmaxf(fmaxf(m0, tmf.x), -1e4f);
        float mn1 = fmaxf(fmaxf(m1, tmf.y), -1e4f);
        float c0 = ex2f(m0 - mn0);
        float c1 = ex2f(m1 - mn1);
        m0 = mn0; m1 = mn1;

        // P = exp2(sf - mn) computed directly in f16x2; ph doubles as the
        // PV A-fragment AND the source for the row sums (exact consistency).
        uint32_t ph[16];
        float rs0 = 0.f, rs1 = 0.f;
#pragma unroll
        for (int jt = 0; jt < 8; jt++) {
            uint32_t p01 = h2ex2(pack_h2(sf[jt][0] - mn0, sf[jt][1] - mn0));
            uint32_t p23 = h2ex2(pack_h2(sf[jt][2] - mn1, sf[jt][3] - mn1));
            ph[jt * 2]     = p01;
            ph[jt * 2 + 1] = p23;
            float2 f01 = h2f2(p01);
            float2 f23 = h2f2(p23);
            rs0 += f01.x + f01.y;
            rs1 += f23.x + f23.y;
        }
        rs0 += __shfl_xor_sync(0xFFFFFFFFu, rs0, 1);
        rs0 += __shfl_xor_sync(0xFFFFFFFFu, rs0, 2);
        rs1 += __shfl_xor_sync(0xFFFFFFFFu, rs1, 1);
        rs1 += __shfl_xor_sync(0xFFFFFFFFu, rs1, 2);
        l0 = l0 * c0 + rs0;
        l1 = l1 * c1 + rs1;

#pragma unroll
        for (int nt = 0; nt < 8; nt++) {
            o[nt][0] *= c0; o[nt][1] *= c0;
            o[nt][2] *= c1; o[nt][3] *= c1;
        }

        // ---- O += P * V ----
        // PV A-fragment for k-step kc: {P[jt=2kc][01], P[jt=2kc][23],
        //                               P[jt=2kc+1][01], P[jt=2kc+1][23]}
#pragma unroll
        for (int kc = 0; kc < 4; kc++) {
            uint32_t pa[4] = {ph[4 * kc], ph[4 * kc + 1],
                              ph[4 * kc + 2], ph[4 * kc + 3]};
#pragma unroll
            for (int dg = 0; dg < 4; dg++) {
                uint32_t vh[4];
                {
                    int r = lane & 7;
                    int row = kc * 16 + r + (((lane >> 3) & 1) << 3);
                    int c = dg * 2 + (lane >> 4);
                    ldmx4t(vh, kst + 8192 + atile_off(row, c));
                }
                mma16816(o[dg * 2 + 0], pa, vh[0], vh[1]);
                mma16816(o[dg * 2 + 1], pa, vh[2], vh[3]);
            }
        }
    }

    const float inv0 = 1.f / l0;
    const float inv1 = 1.f / l1;
    const size_t tok0 = (size_t)(b * SS + qb + qw + gid) * DM;
#pragma unroll
    for (int nt = 0; nt < 8; nt++) {
        int col = h * 64 + nt * 8 + tig * 2;
        *(uint32_t*)(g_ah + tok0 + col) =
            pack_h2(o[nt][0] * inv0, o[nt][1] * inv0);
        *(uint32_t*)(g_ah + tok0 + 8 * DM + col) =
            pack_h2(o[nt][2] * inv1, o[nt][3] * inv1);
    }
}

// ---------------------------------------------------------------------------
extern "C" void kernel_launch(void* const* d_in, const int* in_sizes, int n_in,
                              void* d_out, int out_size)
{
    const float* x  = (const float*)d_in[0];
    const float* Wq = (const float*)d_in[1];
    const float* Wk = (const float*)d_in[2];
    const float* Wv = (const float*)d_in[3];
    const float* Wo = (const float*)d_in[4];
    const float* bo = (const float*)d_in[5];
    float* out = (float*)d_out;

    cudaFuncSetAttribute(qkv_mma,  cudaFuncAttributeMaxDynamicSharedMemorySize, GEMM_SMEM);
    cudaFuncSetAttribute(o_mma,    cudaFuncAttributeMaxDynamicSharedMemorySize, GEMM_SMEM);
    cudaFuncSetAttribute(attn_mma, cudaFuncAttributeMaxDynamicSharedMemorySize, ATTN_SMEM);

    cvt_all<<<dim3(1024, 8), 256>>>(x, Wq, Wk, Wv, Wo);

    dim3 gqkv(DM / 128, MT / 128, 3);
    qkv_mma<<<gqkv, 256, GEMM_SMEM>>>();

    dim3 gattn(SS / 128, BB * NH);
    attn_mma<<<gattn, 256, ATTN_SMEM>>>();

    dim3 go(DM / 128, MT / 128);
    o_mma<<<go, 256, GEMM_SMEM>>>(bo, out);
}